// round 3
// baseline (speedup 1.0000x reference)
#include <cuda_runtime.h>
#include <cuda_bf16.h>
#include <cstdint>
#include <math.h>

// Problem constants
#define BGR   32768      // graphs
#define NPG   54         // nodes per graph
#define EPG   144        // directed edges per graph
#define GLOB  10
#define ACTW  232        // padded activation width (216 embeds + 10 glob + 6 pad)

// Scratch: concatenated activations [BGR][ACTW], pad cols 226..231 (zeroed; unused by K2 math)
__device__ float g_act[(size_t)BGR * ACTW];

// ---------------- f32x2 packed helpers (sm_100+) ----------------
__device__ __forceinline__ unsigned long long pk2(float x, float y) {
    unsigned long long r;
    asm("mov.b64 %0, {%1, %2};" : "=l"(r) : "f"(x), "f"(y));
    return r;
}
__device__ __forceinline__ void fma2(unsigned long long &d, unsigned long long a, unsigned long long b) {
    asm("fma.rn.f32x2 %0, %1, %2, %0;" : "+l"(d) : "l"(a), "l"(b));
}
__device__ __forceinline__ float2 upk(unsigned long long v) {
    float2 f;
    asm("mov.b64 {%0, %1}, %2;" : "=f"(f.x), "=f"(f.y) : "l"(v));
    return f;
}

// =================================================================
// K1: per-graph fused GraphConv x2 + global MLP -> g_act
// One graph per block, 128 threads. All intermediates in shared memory.
// CSR built once per graph with warp-match rank computation (no atomics),
// reused by both conv layers (gather-side aggregation).
// =================================================================
__global__ __launch_bounds__(128)
void k1_graph(const float* __restrict__ x,
              const int*   __restrict__ ei,      // [2][E]
              const float* __restrict__ ea,      // [E]
              const float* __restrict__ gf,      // [B][10]
              const float* __restrict__ W_rel1,  // [8][16]
              const float* __restrict__ b1,      // [16]
              const float* __restrict__ W_root1, // [8][16]
              const float* __restrict__ W_rel2,  // [16][4]
              const float* __restrict__ b2,      // [4]
              const float* __restrict__ W_root2, // [16][4]
              const float* __restrict__ Wg1, const float* __restrict__ bg1,
              const float* __restrict__ Wg2, const float* __restrict__ bg2,
              const float* __restrict__ Wg3, const float* __restrict__ bg3)
{
    __shared__ float4 sx4[NPG * 2];          // x rows [54][8]
    __shared__ int    s_src[EPG], s_dst[EPG];
    __shared__ float  s_attr[EPG];
    __shared__ int    s_cnt[56], s_start[56], s_rank[EPG];
    __shared__ int    s_ssrc[EPG];
    __shared__ float  s_sattr[EPG];
    __shared__ float4 s_agg4[NPG * 2];       // conv1 aggregation [54][8]
    __shared__ float4 s_h1_4[NPG * 4];       // h1 [54][16]
    __shared__ float4 s_agg2_4[NPG * 4];     // conv2 aggregation [54][16]
    __shared__ float  w_rel1[128], w_root1[128], b1s[16];
    __shared__ float  w_rel2[64],  w_root2[64], b2s[4];
    __shared__ float  swg1[80], sbg1[8], swg2[64], sbg2[8], swg3[80], sbg3[10];
    __shared__ float  s_gf[GLOB];

    const int t    = threadIdx.x;
    const int lane = t & 31;
    const int warp = t >> 5;
    const int g    = blockIdx.x;
    float* s_h1 = (float*)s_h1_4;

    const long long E = (long long)BGR * EPG;

    // ---------------- Phase 0: loads ----------------
    if (t < NPG * 2) sx4[t] = ((const float4*)(x + (size_t)g * (NPG * 8)))[t];
    {
        const int base = g * NPG;
        const int* srcp = ei;
        const int* dstp = ei + E;
        for (int i = t; i < EPG; i += 128) {
            s_src[i]  = srcp[(size_t)g * EPG + i] - base;
            s_dst[i]  = dstp[(size_t)g * EPG + i] - base;
            s_attr[i] = ea[(size_t)g * EPG + i];
        }
    }
    if (t < 128) { w_rel1[t] = W_rel1[t]; w_root1[t] = W_root1[t]; }
    if (t < 16)  b1s[t] = b1[t];
    if (t < 64)  { w_rel2[t] = W_rel2[t]; w_root2[t] = W_root2[t]; }
    if (t < 4)   b2s[t] = b2[t];
    if (t < 80)  { swg1[t] = Wg1[t]; swg3[t] = Wg3[t]; }
    if (t < 64)  swg2[t] = Wg2[t];
    if (t < 8)   { sbg1[t] = bg1[t]; sbg2[t] = bg2[t]; }
    if (t < 10)  { sbg3[t] = bg3[t]; s_gf[t] = gf[(size_t)g * GLOB + t]; }
    __syncthreads();

    // ---------------- Phase 1: warp0 = CSR build, warp3 = global MLP ----------------
    if (warp == 0) {
        for (int i = lane; i < 56; i += 32) s_cnt[i] = 0;
        __syncwarp();
        #pragma unroll
        for (int c = 0; c < 5; c++) {
            int e = c * 32 + lane;
            bool valid = (e < EPG);
            int d = valid ? s_dst[e] : 54;      // sentinel bucket (unused)
            unsigned mask = __match_any_sync(0xffffffffu, d);
            int leader = __ffs(mask) - 1;
            int rk = __popc(mask & ((1u << lane) - 1u));
            int basec = s_cnt[d];
            if (valid) s_rank[e] = basec + rk;
            __syncwarp();
            if (lane == leader) s_cnt[d] = basec + __popc(mask);
            __syncwarp();
        }
        if (lane == 0) {
            int acc = 0;
            for (int n = 0; n < NPG; n++) { s_start[n] = acc; acc += s_cnt[n]; }
            s_start[NPG] = acc;
        }
        __syncwarp();
        #pragma unroll
        for (int c = 0; c < 5; c++) {
            int e = c * 32 + lane;
            if (e < EPG) {
                int slot = s_start[s_dst[e]] + s_rank[e];
                s_ssrc[slot]  = s_src[e];
                s_sattr[slot] = s_attr[e];
            }
        }
    } else if (warp == 3) {
        // Global MLP 10 -> 8 -> 8 -> 10 (single warp, shuffle-broadcast)
        float g1 = 0.f;
        if (lane < 8) {
            float a = sbg1[lane];
            #pragma unroll
            for (int i = 0; i < GLOB; i++) a += s_gf[i] * swg1[i * 8 + lane];
            g1 = fmaxf(a, 0.f);
        }
        float a2 = (lane < 8) ? sbg2[lane] : 0.f;
        #pragma unroll
        for (int i = 0; i < 8; i++) {
            float v = __shfl_sync(0xffffffffu, g1, i);
            if (lane < 8) a2 += v * swg2[i * 8 + lane];
        }
        float g2 = fmaxf(a2, 0.f);
        float a3 = (lane < GLOB) ? sbg3[lane] : 0.f;
        #pragma unroll
        for (int i = 0; i < 8; i++) {
            float v = __shfl_sync(0xffffffffu, g2, i);
            if (lane < GLOB) a3 += v * swg3[i * GLOB + lane];
        }
        if (lane < GLOB) g_act[(size_t)g * ACTW + 216 + lane] = fmaxf(a3, 0.f);
        if (lane >= GLOB && lane < 16) g_act[(size_t)g * ACTW + 216 + lane] = 0.f; // pad 226..231
    }
    __syncthreads();

    // ---------------- Phase 2: conv1 aggregation (gather via CSR) ----------------
    if (t < NPG * 2) {
        int n = t >> 1, half = t & 1;
        float4 acc = make_float4(0.f, 0.f, 0.f, 0.f);
        int i0 = s_start[n], i1 = s_start[n + 1];
        for (int i = i0; i < i1; i++) {
            int s = s_ssrc[i];
            float w = s_sattr[i];
            float4 xv = sx4[s * 2 + half];
            acc.x += w * xv.x; acc.y += w * xv.y; acc.z += w * xv.z; acc.w += w * xv.w;
        }
        s_agg4[n * 2 + half] = acc;
    }
    __syncthreads();

    // ---------------- Phase 3: conv1 linear: h1 = relu(agg@Wrel1 + b1 + x@Wroot1) ----------------
    {
        int k = t & 15, ng = t >> 4;
        float wr[8], wo[8];
        #pragma unroll
        for (int f = 0; f < 8; f++) { wr[f] = w_rel1[f * 16 + k]; wo[f] = w_root1[f * 16 + k]; }
        float bb = b1s[k];
        for (int n = ng; n < NPG; n += 8) {
            float4 A0 = s_agg4[n * 2], A1 = s_agg4[n * 2 + 1];
            float4 X0 = sx4[n * 2],   X1 = sx4[n * 2 + 1];
            float acc = bb;
            acc += A0.x * wr[0] + A0.y * wr[1] + A0.z * wr[2] + A0.w * wr[3];
            acc += A1.x * wr[4] + A1.y * wr[5] + A1.z * wr[6] + A1.w * wr[7];
            acc += X0.x * wo[0] + X0.y * wo[1] + X0.z * wo[2] + X0.w * wo[3];
            acc += X1.x * wo[4] + X1.y * wo[5] + X1.z * wo[6] + X1.w * wo[7];
            s_h1[n * 16 + k] = fmaxf(acc, 0.f);
        }
    }
    __syncthreads();

    // ---------------- Phase 4: conv2 aggregation ----------------
    if (t < NPG * 2) {
        int n = t >> 1, half = t & 1;
        float4 a0 = make_float4(0.f, 0.f, 0.f, 0.f);
        float4 a1 = make_float4(0.f, 0.f, 0.f, 0.f);
        int i0 = s_start[n], i1 = s_start[n + 1];
        for (int i = i0; i < i1; i++) {
            int s = s_ssrc[i];
            float w = s_sattr[i];
            float4 h0  = s_h1_4[s * 4 + half * 2];
            float4 h1v = s_h1_4[s * 4 + half * 2 + 1];
            a0.x += w * h0.x;  a0.y += w * h0.y;  a0.z += w * h0.z;  a0.w += w * h0.w;
            a1.x += w * h1v.x; a1.y += w * h1v.y; a1.z += w * h1v.z; a1.w += w * h1v.w;
        }
        s_agg2_4[n * 4 + half * 2]     = a0;
        s_agg2_4[n * 4 + half * 2 + 1] = a1;
    }
    __syncthreads();

    // ---------------- Phase 5: conv2 linear + write embeds ----------------
    if (t < 108) {
        int k = t & 3;   // (t + rep*108) & 3 == t & 3 since 108 % 4 == 0
        float w2r[16], w2o[16];
        #pragma unroll
        for (int f = 0; f < 16; f++) { w2r[f] = w_rel2[f * 4 + k]; w2o[f] = w_root2[f * 4 + k]; }
        float bb = b2s[k];
        #pragma unroll
        for (int rep = 0; rep < 2; rep++) {
            int o = t + rep * 108;
            int n = o >> 2;
            float acc = bb;
            #pragma unroll
            for (int q = 0; q < 4; q++) {
                float4 G = s_agg2_4[n * 4 + q];
                float4 H = s_h1_4[n * 4 + q];
                acc += G.x * w2r[q * 4 + 0] + G.y * w2r[q * 4 + 1] + G.z * w2r[q * 4 + 2] + G.w * w2r[q * 4 + 3];
                acc += H.x * w2o[q * 4 + 0] + H.y * w2o[q * 4 + 1] + H.z * w2o[q * 4 + 2] + H.w * w2o[q * 4 + 3];
            }
            g_act[(size_t)g * ACTW + o] = fmaxf(acc, 0.f);
        }
    }
}

// =================================================================
// K2: out = sigmoid(relu(act @ Wo1 + bo1) @ Wo2 + bo2)
// 64-row x 128-col tile per block; f32x2 packed FMAs; fused epilogue.
// =================================================================
__global__ __launch_bounds__(256)
void k2_outmlp(const float* __restrict__ Wo1,   // [226][128]
               const float* __restrict__ bo1,   // [128]
               const float* __restrict__ Wo2,   // [128]
               const float* __restrict__ bo2,   // [1]
               float* __restrict__ out)         // [B]
{
    __shared__ float sA[8 * 64];
    __shared__ float sW[8 * 128];
    const int tid = threadIdx.x;
    const int tx = tid & 15, ty = tid >> 4;
    const int blockRow = blockIdx.x * 64;
    const int r0 = ty * 4, c0 = tx * 8;

    unsigned long long acc[2][8];
    #pragma unroll
    for (int i = 0; i < 2; i++)
        #pragma unroll
        for (int c = 0; c < 8; c++) acc[i][c] = 0ULL;

    for (int kb = 0; kb < 29; kb++) {
        const int k0 = kb * 8;
        if (tid < 128) {
            int row = tid & 63, kq = tid >> 6;
            float4 v = *(const float4*)(g_act + (size_t)(blockRow + row) * ACTW + k0 + kq * 4);
            sA[(kq * 4 + 0) * 64 + row] = v.x;
            sA[(kq * 4 + 1) * 64 + row] = v.y;
            sA[(kq * 4 + 2) * 64 + row] = v.z;
            sA[(kq * 4 + 3) * 64 + row] = v.w;
        }
        {
            int kk = tid >> 5, c4 = (tid & 31) * 4;
            int k = k0 + kk;
            float4 w = (k < 226) ? *(const float4*)(Wo1 + (size_t)k * 128 + c4)
                                 : make_float4(0.f, 0.f, 0.f, 0.f);
            *(float4*)(sW + kk * 128 + c4) = w;
        }
        __syncthreads();
        #pragma unroll
        for (int kk = 0; kk < 8; kk++) {
            float4 av = *(const float4*)(sA + kk * 64 + r0);
            float4 w0 = *(const float4*)(sW + kk * 128 + c0);
            float4 w1 = *(const float4*)(sW + kk * 128 + c0 + 4);
            unsigned long long a01 = pk2(av.x, av.y);
            unsigned long long a23 = pk2(av.z, av.w);
            float wc[8] = {w0.x, w0.y, w0.z, w0.w, w1.x, w1.y, w1.z, w1.w};
            #pragma unroll
            for (int c = 0; c < 8; c++) {
                unsigned long long wd = pk2(wc[c], wc[c]);
                fma2(acc[0][c], a01, wd);
                fma2(acc[1][c], a23, wd);
            }
        }
        __syncthreads();
    }

    // Epilogue: relu + dot with Wo2, reduce across 16 col-threads, sigmoid.
    float b1v[8], w2v[8];
    #pragma unroll
    for (int c = 0; c < 8; c++) { b1v[c] = bo1[c0 + c]; w2v[c] = Wo2[c0 + c]; }
    float p[4] = {0.f, 0.f, 0.f, 0.f};
    #pragma unroll
    for (int c = 0; c < 8; c++) {
        float2 v0 = upk(acc[0][c]);
        float2 v1 = upk(acc[1][c]);
        p[0] += fmaxf(v0.x + b1v[c], 0.f) * w2v[c];
        p[1] += fmaxf(v0.y + b1v[c], 0.f) * w2v[c];
        p[2] += fmaxf(v1.x + b1v[c], 0.f) * w2v[c];
        p[3] += fmaxf(v1.y + b1v[c], 0.f) * w2v[c];
    }
    #pragma unroll
    for (int j = 0; j < 4; j++) {
        #pragma unroll
        for (int off = 8; off > 0; off >>= 1)
            p[j] += __shfl_xor_sync(0xffffffffu, p[j], off, 16);
    }
    if (tx == 0) {
        float bb = bo2[0];
        #pragma unroll
        for (int j = 0; j < 4; j++) {
            float z = p[j] + bb;
            out[blockRow + r0 + j] = 1.f / (1.f + expf(-z));
        }
    }
}

extern "C" void kernel_launch(void* const* d_in, const int* in_sizes, int n_in,
                              void* d_out, int out_size)
{
    const float* x       = (const float*)d_in[0];
    const int*   ei      = (const int*)  d_in[1];
    const float* ea      = (const float*)d_in[2];
    const float* gf      = (const float*)d_in[3];
    const float* W_rel1  = (const float*)d_in[4];
    const float* b1      = (const float*)d_in[5];
    const float* W_root1 = (const float*)d_in[6];
    const float* W_rel2  = (const float*)d_in[7];
    const float* b2      = (const float*)d_in[8];
    const float* W_root2 = (const float*)d_in[9];
    const float* Wg1     = (const float*)d_in[10];
    const float* bg1     = (const float*)d_in[11];
    const float* Wg2     = (const float*)d_in[12];
    const float* bg2     = (const float*)d_in[13];
    const float* Wg3     = (const float*)d_in[14];
    const float* bg3     = (const float*)d_in[15];
    const float* Wo1     = (const float*)d_in[16];
    const float* bo1     = (const float*)d_in[17];
    const float* Wo2     = (const float*)d_in[18];
    const float* bo2     = (const float*)d_in[19];
    float* out = (float*)d_out;

    k1_graph<<<BGR, 128>>>(x, ei, ea, gf,
                           W_rel1, b1, W_root1,
                           W_rel2, b2, W_root2,
                           Wg1, bg1, Wg2, bg2, Wg3, bg3);
    k2_outmlp<<<BGR / 64, 256>>>(Wo1, bo1, Wo2, bo2, out);
}

// round 4
// speedup vs baseline: 1.0955x; 1.0955x over previous
#include <cuda_runtime.h>
#include <cuda_bf16.h>
#include <cstdint>
#include <math.h>

// Problem constants
#define BGR   32768      // graphs
#define NPG   54         // nodes per graph
#define EPG   144        // directed edges per graph
#define GLOB  10
#define ACTW  240        // padded activation width (216 embeds + 10 glob + 14 pad) = 15*16
#define KCH   16         // K-chunk for K2

// Scratch: concatenated activations [BGR][ACTW]; cols 226..239 zeroed
__device__ float g_act[(size_t)BGR * ACTW];

// ---------------- f32x2 packed helpers (sm_100+) ----------------
__device__ __forceinline__ unsigned long long pk2(float x, float y) {
    unsigned long long r;
    asm("mov.b64 %0, {%1, %2};" : "=l"(r) : "f"(x), "f"(y));
    return r;
}
__device__ __forceinline__ void fma2(unsigned long long &d, unsigned long long a, unsigned long long b) {
    asm("fma.rn.f32x2 %0, %1, %2, %0;" : "+l"(d) : "l"(a), "l"(b));
}
__device__ __forceinline__ float2 upk(unsigned long long v) {
    float2 f;
    asm("mov.b64 {%0, %1}, %2;" : "=f"(f.x), "=f"(f.y) : "l"(v));
    return f;
}

// =================================================================
// K1: per-graph fused GraphConv x2 + global MLP -> g_act
// =================================================================
__global__ __launch_bounds__(128)
void k1_graph(const float* __restrict__ x,
              const int*   __restrict__ ei,      // [2][E]
              const float* __restrict__ ea,      // [E]
              const float* __restrict__ gf,      // [B][10]
              const float* __restrict__ W_rel1,  // [8][16]
              const float* __restrict__ b1,      // [16]
              const float* __restrict__ W_root1, // [8][16]
              const float* __restrict__ W_rel2,  // [16][4]
              const float* __restrict__ b2,      // [4]
              const float* __restrict__ W_root2, // [16][4]
              const float* __restrict__ Wg1, const float* __restrict__ bg1,
              const float* __restrict__ Wg2, const float* __restrict__ bg2,
              const float* __restrict__ Wg3, const float* __restrict__ bg3)
{
    __shared__ float4 sx4[NPG * 2];          // x rows [54][8]
    __shared__ int    s_src[EPG], s_dst[EPG];
    __shared__ float  s_attr[EPG];
    __shared__ int    s_cnt[56], s_start[56], s_rank[EPG];
    __shared__ int    s_ssrc[EPG];
    __shared__ float  s_sattr[EPG];
    __shared__ float4 s_agg4[NPG * 2];       // conv1 aggregation [54][8]
    __shared__ float4 s_h1_4[NPG * 4];       // h1 [54][16]
    __shared__ float4 s_agg2_4[NPG * 4];     // conv2 aggregation [54][16]
    __shared__ float  w_rel1[128], w_root1[128], b1s[16];
    __shared__ float  w_rel2[64],  w_root2[64], b2s[4];
    __shared__ float  swg1[80], sbg1[8], swg2[64], sbg2[8], swg3[80], sbg3[10];
    __shared__ float  s_gf[GLOB];

    const int t    = threadIdx.x;
    const int lane = t & 31;
    const int warp = t >> 5;
    const int g    = blockIdx.x;
    float* s_h1 = (float*)s_h1_4;

    const long long E = (long long)BGR * EPG;

    // ---------------- Phase 0: loads (vectorized) ----------------
    if (t < NPG * 2) sx4[t] = ((const float4*)(x + (size_t)g * (NPG * 8)))[t];
    {
        const int base = g * NPG;
        if (t < 36) {                       // src: 144 ints = 36 int4
            int4 v = ((const int4*)(ei + (size_t)g * EPG))[t];
            s_src[t * 4 + 0] = v.x - base;
            s_src[t * 4 + 1] = v.y - base;
            s_src[t * 4 + 2] = v.z - base;
            s_src[t * 4 + 3] = v.w - base;
        } else if (t < 72) {                // dst
            int i = t - 36;
            int4 v = ((const int4*)(ei + E + (size_t)g * EPG))[i];
            s_dst[i * 4 + 0] = v.x - base;
            s_dst[i * 4 + 1] = v.y - base;
            s_dst[i * 4 + 2] = v.z - base;
            s_dst[i * 4 + 3] = v.w - base;
        } else if (t < 108) {               // attr
            int i = t - 72;
            float4 v = ((const float4*)(ea + (size_t)g * EPG))[i];
            s_attr[i * 4 + 0] = v.x;
            s_attr[i * 4 + 1] = v.y;
            s_attr[i * 4 + 2] = v.z;
            s_attr[i * 4 + 3] = v.w;
        }
    }
    if (t < 128) { w_rel1[t] = W_rel1[t]; w_root1[t] = W_root1[t]; }
    if (t < 16)  b1s[t] = b1[t];
    if (t < 64)  { w_rel2[t] = W_rel2[t]; w_root2[t] = W_root2[t]; }
    if (t < 4)   b2s[t] = b2[t];
    if (t < 80)  { swg1[t] = Wg1[t]; swg3[t] = Wg3[t]; }
    if (t < 64)  swg2[t] = Wg2[t];
    if (t < 8)   { sbg1[t] = bg1[t]; sbg2[t] = bg2[t]; }
    if (t < 10)  { sbg3[t] = bg3[t]; s_gf[t] = gf[(size_t)g * GLOB + t]; }
    __syncthreads();

    // ---------------- Phase 1: warp0 = CSR build, warp3 = global MLP ----------------
    if (warp == 0) {
        for (int i = lane; i < 56; i += 32) s_cnt[i] = 0;
        __syncwarp();
        #pragma unroll
        for (int c = 0; c < 5; c++) {
            int e = c * 32 + lane;
            bool valid = (e < EPG);
            int d = valid ? s_dst[e] : 54;      // sentinel bucket (unused)
            unsigned mask = __match_any_sync(0xffffffffu, d);
            int leader = __ffs(mask) - 1;
            int rk = __popc(mask & ((1u << lane) - 1u));
            int basec = s_cnt[d];
            if (valid) s_rank[e] = basec + rk;
            __syncwarp();
            if (lane == leader) s_cnt[d] = basec + __popc(mask);
            __syncwarp();
        }
        // Warp-parallel exclusive prefix scan of s_cnt[0..53] -> s_start[0..54]
        {
            int v0 = (lane < NPG) ? s_cnt[lane] : 0;
            int v1 = (lane + 32 < NPG) ? s_cnt[lane + 32] : 0;
            int s0 = v0, s1 = v1;
            #pragma unroll
            for (int off = 1; off < 32; off <<= 1) {
                int n0 = __shfl_up_sync(0xffffffffu, s0, off);
                int n1 = __shfl_up_sync(0xffffffffu, s1, off);
                if (lane >= off) { s0 += n0; s1 += n1; }
            }
            int total0 = __shfl_sync(0xffffffffu, s0, 31);
            s_start[lane] = s0 - v0;
            if (lane + 32 <= NPG) s_start[lane + 32] = total0 + s1 - v1;
        }
        __syncwarp();
        #pragma unroll
        for (int c = 0; c < 5; c++) {
            int e = c * 32 + lane;
            if (e < EPG) {
                int slot = s_start[s_dst[e]] + s_rank[e];
                s_ssrc[slot]  = s_src[e];
                s_sattr[slot] = s_attr[e];
            }
        }
    } else if (warp == 3) {
        // Global MLP 10 -> 8 -> 8 -> 10 (single warp, shuffle-broadcast)
        float g1 = 0.f;
        if (lane < 8) {
            float a = sbg1[lane];
            #pragma unroll
            for (int i = 0; i < GLOB; i++) a += s_gf[i] * swg1[i * 8 + lane];
            g1 = fmaxf(a, 0.f);
        }
        float a2 = (lane < 8) ? sbg2[lane] : 0.f;
        #pragma unroll
        for (int i = 0; i < 8; i++) {
            float v = __shfl_sync(0xffffffffu, g1, i);
            if (lane < 8) a2 += v * swg2[i * 8 + lane];
        }
        float g2 = fmaxf(a2, 0.f);
        float a3 = (lane < GLOB) ? sbg3[lane] : 0.f;
        #pragma unroll
        for (int i = 0; i < 8; i++) {
            float v = __shfl_sync(0xffffffffu, g2, i);
            if (lane < GLOB) a3 += v * swg3[i * GLOB + lane];
        }
        if (lane < GLOB) g_act[(size_t)g * ACTW + 216 + lane] = fmaxf(a3, 0.f);
        if (lane >= GLOB && lane < 24) g_act[(size_t)g * ACTW + 216 + lane] = 0.f; // pad 226..239
    }
    __syncthreads();

    // ---------------- Phase 2: conv1 aggregation (gather via CSR) ----------------
    if (t < NPG * 2) {
        int n = t >> 1, half = t & 1;
        float4 acc = make_float4(0.f, 0.f, 0.f, 0.f);
        int i0 = s_start[n], i1 = s_start[n + 1];
        for (int i = i0; i < i1; i++) {
            int s = s_ssrc[i];
            float w = s_sattr[i];
            float4 xv = sx4[s * 2 + half];
            acc.x += w * xv.x; acc.y += w * xv.y; acc.z += w * xv.z; acc.w += w * xv.w;
        }
        s_agg4[n * 2 + half] = acc;
    }
    __syncthreads();

    // ---------------- Phase 3: conv1 linear: h1 = relu(agg@Wrel1 + b1 + x@Wroot1) ----------------
    {
        int k = t & 15, ng = t >> 4;
        float wr[8], wo[8];
        #pragma unroll
        for (int f = 0; f < 8; f++) { wr[f] = w_rel1[f * 16 + k]; wo[f] = w_root1[f * 16 + k]; }
        float bb = b1s[k];
        for (int n = ng; n < NPG; n += 8) {
            float4 A0 = s_agg4[n * 2], A1 = s_agg4[n * 2 + 1];
            float4 X0 = sx4[n * 2],   X1 = sx4[n * 2 + 1];
            float acc = bb;
            acc += A0.x * wr[0] + A0.y * wr[1] + A0.z * wr[2] + A0.w * wr[3];
            acc += A1.x * wr[4] + A1.y * wr[5] + A1.z * wr[6] + A1.w * wr[7];
            acc += X0.x * wo[0] + X0.y * wo[1] + X0.z * wo[2] + X0.w * wo[3];
            acc += X1.x * wo[4] + X1.y * wo[5] + X1.z * wo[6] + X1.w * wo[7];
            s_h1[n * 16 + k] = fmaxf(acc, 0.f);
        }
    }
    __syncthreads();

    // ---------------- Phase 4: conv2 aggregation ----------------
    if (t < NPG * 2) {
        int n = t >> 1, half = t & 1;
        float4 a0 = make_float4(0.f, 0.f, 0.f, 0.f);
        float4 a1 = make_float4(0.f, 0.f, 0.f, 0.f);
        int i0 = s_start[n], i1 = s_start[n + 1];
        for (int i = i0; i < i1; i++) {
            int s = s_ssrc[i];
            float w = s_sattr[i];
            float4 h0  = s_h1_4[s * 4 + half * 2];
            float4 h1v = s_h1_4[s * 4 + half * 2 + 1];
            a0.x += w * h0.x;  a0.y += w * h0.y;  a0.z += w * h0.z;  a0.w += w * h0.w;
            a1.x += w * h1v.x; a1.y += w * h1v.y; a1.z += w * h1v.z; a1.w += w * h1v.w;
        }
        s_agg2_4[n * 4 + half * 2]     = a0;
        s_agg2_4[n * 4 + half * 2 + 1] = a1;
    }
    __syncthreads();

    // ---------------- Phase 5: conv2 linear + write embeds ----------------
    if (t < 108) {
        int k = t & 3;   // (t + rep*108) & 3 == t & 3 since 108 % 4 == 0
        float w2r[16], w2o[16];
        #pragma unroll
        for (int f = 0; f < 16; f++) { w2r[f] = w_rel2[f * 4 + k]; w2o[f] = w_root2[f * 4 + k]; }
        float bb = b2s[k];
        #pragma unroll
        for (int rep = 0; rep < 2; rep++) {
            int o = t + rep * 108;
            int n = o >> 2;
            float acc = bb;
            #pragma unroll
            for (int q = 0; q < 4; q++) {
                float4 G = s_agg2_4[n * 4 + q];
                float4 H = s_h1_4[n * 4 + q];
                acc += G.x * w2r[q * 4 + 0] + G.y * w2r[q * 4 + 1] + G.z * w2r[q * 4 + 2] + G.w * w2r[q * 4 + 3];
                acc += H.x * w2o[q * 4 + 0] + H.y * w2o[q * 4 + 1] + H.z * w2o[q * 4 + 2] + H.w * w2o[q * 4 + 3];
            }
            g_act[(size_t)g * ACTW + o] = fmaxf(acc, 0.f);
        }
    }
}

// =================================================================
// K2: out = sigmoid(relu(act @ Wo1 + bo1) @ Wo2 + bo2)
// 32-row x 128-col tile per block (grid 1024 x 128 thr).
// Weight pairs read directly as ulonglong2 from shared (no packing movs).
// =================================================================
__global__ __launch_bounds__(128)
void k2_outmlp(const float* __restrict__ Wo1,   // [226][128]
               const float* __restrict__ bo1,   // [128]
               const float* __restrict__ Wo2,   // [128]
               const float* __restrict__ bo2,   // [1]
               float* __restrict__ out)         // [B]
{
    __shared__ float sA[KCH * 32];    // [kk][row]
    __shared__ float sW[KCH * 128];   // [kk][col]
    const int tid = threadIdx.x;
    const int tx = tid & 15, ty = tid >> 4;
    const int blockRow = blockIdx.x * 32;
    const int r0 = ty * 4, c0 = tx * 8;

    unsigned long long acc[4][4];
    #pragma unroll
    for (int r = 0; r < 4; r++)
        #pragma unroll
        for (int cp = 0; cp < 4; cp++) acc[r][cp] = 0ULL;

    const int arow = tid & 31, akq = tid >> 5;
    const float* aptr = g_act + (size_t)(blockRow + arow) * ACTW + akq * 4;

    for (int kb = 0; kb < 15; kb++) {
        const int k0 = kb * KCH;
        // A tile: 32 rows x 16 k (transposed store, conflict-free)
        {
            float4 v = *(const float4*)(aptr + k0);
            sA[(akq * 4 + 0) * 32 + arow] = v.x;
            sA[(akq * 4 + 1) * 32 + arow] = v.y;
            sA[(akq * 4 + 2) * 32 + arow] = v.z;
            sA[(akq * 4 + 3) * 32 + arow] = v.w;
        }
        // W tile: 16 k x 128 cols (4 float4 per thread), zero-fill k >= 226
        #pragma unroll
        for (int q = 0; q < 4; q++) {
            int idx = tid + q * 128;
            int kk = idx >> 5, c4 = (idx & 31) * 4;
            int k = k0 + kk;
            float4 w = (k < 226) ? *(const float4*)(Wo1 + (size_t)k * 128 + c4)
                                 : make_float4(0.f, 0.f, 0.f, 0.f);
            *(float4*)(sW + kk * 128 + c4) = w;
        }
        __syncthreads();
        #pragma unroll
        for (int kk = 0; kk < KCH; kk++) {
            float4 a = *(const float4*)(sA + kk * 32 + r0);
            ulonglong2 wA = *(const ulonglong2*)(sW + kk * 128 + c0);
            ulonglong2 wB = *(const ulonglong2*)(sW + kk * 128 + c0 + 4);
            unsigned long long ad0 = pk2(a.x, a.x);
            unsigned long long ad1 = pk2(a.y, a.y);
            unsigned long long ad2 = pk2(a.z, a.z);
            unsigned long long ad3 = pk2(a.w, a.w);
            fma2(acc[0][0], ad0, wA.x); fma2(acc[0][1], ad0, wA.y);
            fma2(acc[0][2], ad0, wB.x); fma2(acc[0][3], ad0, wB.y);
            fma2(acc[1][0], ad1, wA.x); fma2(acc[1][1], ad1, wA.y);
            fma2(acc[1][2], ad1, wB.x); fma2(acc[1][3], ad1, wB.y);
            fma2(acc[2][0], ad2, wA.x); fma2(acc[2][1], ad2, wA.y);
            fma2(acc[2][2], ad2, wB.x); fma2(acc[2][3], ad2, wB.y);
            fma2(acc[3][0], ad3, wA.x); fma2(acc[3][1], ad3, wA.y);
            fma2(acc[3][2], ad3, wB.x); fma2(acc[3][3], ad3, wB.y);
        }
        __syncthreads();
    }

    // Epilogue: relu + dot with Wo2, reduce across 16 col-threads, sigmoid.
    float b1v[8], w2v[8];
    #pragma unroll
    for (int c = 0; c < 8; c++) { b1v[c] = bo1[c0 + c]; w2v[c] = Wo2[c0 + c]; }
    float p[4];
    #pragma unroll
    for (int r = 0; r < 4; r++) {
        p[r] = 0.f;
        #pragma unroll
        for (int cp = 0; cp < 4; cp++) {
            float2 v = upk(acc[r][cp]);
            p[r] += fmaxf(v.x + b1v[2 * cp],     0.f) * w2v[2 * cp];
            p[r] += fmaxf(v.y + b1v[2 * cp + 1], 0.f) * w2v[2 * cp + 1];
        }
    }
    #pragma unroll
    for (int r = 0; r < 4; r++) {
        #pragma unroll
        for (int off = 8; off > 0; off >>= 1)
            p[r] += __shfl_xor_sync(0xffffffffu, p[r], off, 16);
    }
    if (tx == 0) {
        float bb = bo2[0];
        #pragma unroll
        for (int r = 0; r < 4; r++) {
            float z = p[r] + bb;
            out[blockRow + r0 + r] = 1.f / (1.f + expf(-z));
        }
    }
}

extern "C" void kernel_launch(void* const* d_in, const int* in_sizes, int n_in,
                              void* d_out, int out_size)
{
    const float* x       = (const float*)d_in[0];
    const int*   ei      = (const int*)  d_in[1];
    const float* ea      = (const float*)d_in[2];
    const float* gf      = (const float*)d_in[3];
    const float* W_rel1  = (const float*)d_in[4];
    const float* b1      = (const float*)d_in[5];
    const float* W_root1 = (const float*)d_in[6];
    const float* W_rel2  = (const float*)d_in[7];
    const float* b2      = (const float*)d_in[8];
    const float* W_root2 = (const float*)d_in[9];
    const float* Wg1     = (const float*)d_in[10];
    const float* bg1     = (const float*)d_in[11];
    const float* Wg2     = (const float*)d_in[12];
    const float* bg2     = (const float*)d_in[13];
    const float* Wg3     = (const float*)d_in[14];
    const float* bg3     = (const float*)d_in[15];
    const float* Wo1     = (const float*)d_in[16];
    const float* bo1     = (const float*)d_in[17];
    const float* Wo2     = (const float*)d_in[18];
    const float* bo2     = (const float*)d_in[19];
    float* out = (float*)d_out;

    k1_graph<<<BGR, 128>>>(x, ei, ea, gf,
                           W_rel1, b1, W_root1,
                           W_rel2, b2, W_root2,
                           Wg1, bg1, Wg2, bg2, Wg3, bg3);
    k2_outmlp<<<BGR / 32, 128>>>(Wo1, bo1, Wo2, bo2, out);
}

// round 5
// speedup vs baseline: 1.1721x; 1.0699x over previous
#include <cuda_runtime.h>
#include <cuda_bf16.h>
#include <cstdint>
#include <math.h>

// Problem constants
#define BGR   32768      // graphs
#define NPG   54         // nodes per graph
#define EPG   144        // directed edges per graph
#define GLOB  10
#define ACTW  240        // padded activation width (216 embeds + 10 glob + 14 pad) = 15*16
#define KCH   16         // K-chunk for K2

// Scratch: concatenated activations [BGR][ACTW]; cols 226..239 zeroed
__device__ float g_act[(size_t)BGR * ACTW];

// ---------------- f32x2 packed helpers (sm_100+) ----------------
__device__ __forceinline__ unsigned long long pk2(float x, float y) {
    unsigned long long r;
    asm("mov.b64 %0, {%1, %2};" : "=l"(r) : "f"(x), "f"(y));
    return r;
}
__device__ __forceinline__ void fma2(unsigned long long &d, unsigned long long a, unsigned long long b) {
    asm("fma.rn.f32x2 %0, %1, %2, %0;" : "+l"(d) : "l"(a), "l"(b));
}
__device__ __forceinline__ float2 upk(unsigned long long v) {
    float2 f;
    asm("mov.b64 {%0, %1}, %2;" : "=f"(f.x), "=f"(f.y) : "l"(v));
    return f;
}

// =================================================================
// K1: per-graph fused GraphConv x2 + global MLP -> g_act
// 3 barriers total. Each (node,half) thread aggregates in registers and
// computes the half-partial of the linear layer; shfl_xor(1) completes it.
// =================================================================
__global__ __launch_bounds__(128)
void k1_graph(const float* __restrict__ x,
              const int*   __restrict__ ei,      // [2][E]
              const float* __restrict__ ea,      // [E]
              const float* __restrict__ gf,      // [B][10]
              const float* __restrict__ W_rel1,  // [8][16]
              const float* __restrict__ b1,      // [16]
              const float* __restrict__ W_root1, // [8][16]
              const float* __restrict__ W_rel2,  // [16][4]
              const float* __restrict__ b2,      // [4]
              const float* __restrict__ W_root2, // [16][4]
              const float* __restrict__ Wg1, const float* __restrict__ bg1,
              const float* __restrict__ Wg2, const float* __restrict__ bg2,
              const float* __restrict__ Wg3, const float* __restrict__ bg3)
{
    __shared__ __align__(16) float4 sx4[NPG * 2];      // x rows [54][8]
    __shared__ int    s_src[EPG], s_dst[EPG];
    __shared__ float  s_attr[EPG];
    __shared__ int    s_cnt[56], s_start[56], s_rank[EPG];
    __shared__ __align__(8)  float2 s_sedge[EPG];      // {attr, src_as_float}
    __shared__ __align__(16) float4 s_h1_4[NPG * 4];   // h1 [54][16]
    __shared__ __align__(16) float  w_rel1[128], w_root1[128];
    __shared__ float  b1s[16];
    __shared__ __align__(16) float  w_rel2[64],  w_root2[64];
    __shared__ float  b2s[4];
    __shared__ float  swg1[80], sbg1[8], swg2[64], sbg2[8], swg3[80], sbg3[10];
    __shared__ float  s_gf[GLOB];

    const int t    = threadIdx.x;
    const int lane = t & 31;
    const int warp = t >> 5;
    const int g    = blockIdx.x;

    const long long E = (long long)BGR * EPG;

    // ---------------- Phase 0: loads (vectorized) ----------------
    if (t < NPG * 2) sx4[t] = ((const float4*)(x + (size_t)g * (NPG * 8)))[t];
    {
        const int base = g * NPG;
        if (t < 36) {                       // src: 144 ints = 36 int4
            int4 v = ((const int4*)(ei + (size_t)g * EPG))[t];
            s_src[t * 4 + 0] = v.x - base;
            s_src[t * 4 + 1] = v.y - base;
            s_src[t * 4 + 2] = v.z - base;
            s_src[t * 4 + 3] = v.w - base;
        } else if (t < 72) {                // dst
            int i = t - 36;
            int4 v = ((const int4*)(ei + E + (size_t)g * EPG))[i];
            s_dst[i * 4 + 0] = v.x - base;
            s_dst[i * 4 + 1] = v.y - base;
            s_dst[i * 4 + 2] = v.z - base;
            s_dst[i * 4 + 3] = v.w - base;
        } else if (t < 108) {               // attr
            int i = t - 72;
            float4 v = ((const float4*)(ea + (size_t)g * EPG))[i];
            s_attr[i * 4 + 0] = v.x;
            s_attr[i * 4 + 1] = v.y;
            s_attr[i * 4 + 2] = v.z;
            s_attr[i * 4 + 3] = v.w;
        }
    }
    if (t < 128) { w_rel1[t] = W_rel1[t]; w_root1[t] = W_root1[t]; }
    if (t < 16)  b1s[t] = b1[t];
    if (t < 64)  { w_rel2[t] = W_rel2[t]; w_root2[t] = W_root2[t]; }
    if (t < 4)   b2s[t] = b2[t];
    if (t < 80)  { swg1[t] = Wg1[t]; swg3[t] = Wg3[t]; }
    if (t < 64)  swg2[t] = Wg2[t];
    if (t < 8)   { sbg1[t] = bg1[t]; sbg2[t] = bg2[t]; }
    if (t < 10)  { sbg3[t] = bg3[t]; s_gf[t] = gf[(size_t)g * GLOB + t]; }
    __syncthreads();

    // ---------------- Phase 1: warp0 = CSR build, warp3 = global MLP ----------------
    if (warp == 0) {
        for (int i = lane; i < 56; i += 32) s_cnt[i] = 0;
        __syncwarp();
        #pragma unroll
        for (int c = 0; c < 5; c++) {
            int e = c * 32 + lane;
            bool valid = (e < EPG);
            int d = valid ? s_dst[e] : 54;      // sentinel bucket (unused)
            unsigned mask = __match_any_sync(0xffffffffu, d);
            int leader = __ffs(mask) - 1;
            int rk = __popc(mask & ((1u << lane) - 1u));
            int basec = s_cnt[d];
            if (valid) s_rank[e] = basec + rk;
            __syncwarp();
            if (lane == leader) s_cnt[d] = basec + __popc(mask);
            __syncwarp();
        }
        // Warp-parallel exclusive prefix scan of s_cnt[0..53] -> s_start[0..54]
        {
            int v0 = (lane < NPG) ? s_cnt[lane] : 0;
            int v1 = (lane + 32 < NPG) ? s_cnt[lane + 32] : 0;
            int s0 = v0, s1 = v1;
            #pragma unroll
            for (int off = 1; off < 32; off <<= 1) {
                int n0 = __shfl_up_sync(0xffffffffu, s0, off);
                int n1 = __shfl_up_sync(0xffffffffu, s1, off);
                if (lane >= off) { s0 += n0; s1 += n1; }
            }
            int total0 = __shfl_sync(0xffffffffu, s0, 31);
            s_start[lane] = s0 - v0;
            if (lane + 32 <= NPG) s_start[lane + 32] = total0 + s1 - v1;
        }
        __syncwarp();
        #pragma unroll
        for (int c = 0; c < 5; c++) {
            int e = c * 32 + lane;
            if (e < EPG) {
                int slot = s_start[s_dst[e]] + s_rank[e];
                s_sedge[slot] = make_float2(s_attr[e], __int_as_float(s_src[e]));
            }
        }
    } else if (warp == 3) {
        // Global MLP 10 -> 8 -> 8 -> 10 (single warp, shuffle-broadcast)
        float g1 = 0.f;
        if (lane < 8) {
            float a = sbg1[lane];
            #pragma unroll
            for (int i = 0; i < GLOB; i++) a += s_gf[i] * swg1[i * 8 + lane];
            g1 = fmaxf(a, 0.f);
        }
        float a2 = (lane < 8) ? sbg2[lane] : 0.f;
        #pragma unroll
        for (int i = 0; i < 8; i++) {
            float v = __shfl_sync(0xffffffffu, g1, i);
            if (lane < 8) a2 += v * swg2[i * 8 + lane];
        }
        float g2 = fmaxf(a2, 0.f);
        float a3 = (lane < GLOB) ? sbg3[lane] : 0.f;
        #pragma unroll
        for (int i = 0; i < 8; i++) {
            float v = __shfl_sync(0xffffffffu, g2, i);
            if (lane < GLOB) a3 += v * swg3[i * GLOB + lane];
        }
        if (lane < GLOB) g_act[(size_t)g * ACTW + 216 + lane] = fmaxf(a3, 0.f);
        if (lane >= GLOB && lane < 24) g_act[(size_t)g * ACTW + 216 + lane] = 0.f; // pad 226..239
    }
    __syncthreads();

    // ---------------- Phase 2: fused conv1 agg + linear -> h1 ----------------
    if (t < NPG * 2) {
        const int n = t >> 1, half = t & 1;
        float4 agg = make_float4(0.f, 0.f, 0.f, 0.f);
        const int i0 = s_start[n], i1 = s_start[n + 1];
        for (int i = i0; i < i1; i++) {
            float2 e = s_sedge[i];
            int s = __float_as_int(e.y);
            float w = e.x;
            float4 xv = sx4[s * 2 + half];
            agg.x += w * xv.x; agg.y += w * xv.y; agg.z += w * xv.z; agg.w += w * xv.w;
        }
        float4 xo = sx4[n * 2 + half];
        float av[4] = {agg.x, agg.y, agg.z, agg.w};
        float xv2[4] = {xo.x, xo.y, xo.z, xo.w};

        unsigned long long acc[8];
        #pragma unroll
        for (int p = 0; p < 8; p++)
            acc[p] = (half == 0) ? pk2(b1s[2 * p], b1s[2 * p + 1]) : 0ULL;

        #pragma unroll
        for (int f = 0; f < 4; f++) {
            const int row = half * 4 + f;
            unsigned long long ad = pk2(av[f], av[f]);
            unsigned long long xd = pk2(xv2[f], xv2[f]);
            const ulonglong2* wr = (const ulonglong2*)(w_rel1 + row * 16);
            const ulonglong2* wo = (const ulonglong2*)(w_root1 + row * 16);
            ulonglong2 r0 = wr[0], r1 = wr[1], r2 = wr[2], r3 = wr[3];
            ulonglong2 o0 = wo[0], o1 = wo[1], o2 = wo[2], o3 = wo[3];
            fma2(acc[0], ad, r0.x); fma2(acc[1], ad, r0.y);
            fma2(acc[2], ad, r1.x); fma2(acc[3], ad, r1.y);
            fma2(acc[4], ad, r2.x); fma2(acc[5], ad, r2.y);
            fma2(acc[6], ad, r3.x); fma2(acc[7], ad, r3.y);
            fma2(acc[0], xd, o0.x); fma2(acc[1], xd, o0.y);
            fma2(acc[2], xd, o1.x); fma2(acc[3], xd, o1.y);
            fma2(acc[4], xd, o2.x); fma2(acc[5], xd, o2.y);
            fma2(acc[6], xd, o3.x); fma2(acc[7], xd, o3.y);
        }
        // pair reduction across (half=0, half=1) lanes, then relu + store
        unsigned m = __activemask();
        float h[16];
        #pragma unroll
        for (int p = 0; p < 8; p++) {
            float2 v = upk(acc[p]);
            h[2 * p]     = v.x;
            h[2 * p + 1] = v.y;
        }
        #pragma unroll
        for (int j = 0; j < 16; j++)
            h[j] = fmaxf(h[j] + __shfl_xor_sync(m, h[j], 1), 0.f);
        float* hp = (float*)s_h1_4 + n * 16 + half * 8;
        *(float4*)(hp)     = make_float4(h[half * 8 + 0], h[half * 8 + 1], h[half * 8 + 2], h[half * 8 + 3]);
        *(float4*)(hp + 4) = make_float4(h[half * 8 + 4], h[half * 8 + 5], h[half * 8 + 6], h[half * 8 + 7]);
    }
    __syncthreads();

    // ---------------- Phase 3: fused conv2 agg + linear -> g_act ----------------
    if (t < NPG * 2) {
        const int n = t >> 1, half = t & 1;
        float4 a0 = make_float4(0.f, 0.f, 0.f, 0.f);
        float4 a1 = make_float4(0.f, 0.f, 0.f, 0.f);
        const int i0 = s_start[n], i1 = s_start[n + 1];
        for (int i = i0; i < i1; i++) {
            float2 e = s_sedge[i];
            int s = __float_as_int(e.y);
            float w = e.x;
            float4 h0  = s_h1_4[s * 4 + half * 2];
            float4 h1v = s_h1_4[s * 4 + half * 2 + 1];
            a0.x += w * h0.x;  a0.y += w * h0.y;  a0.z += w * h0.z;  a0.w += w * h0.w;
            a1.x += w * h1v.x; a1.y += w * h1v.y; a1.z += w * h1v.z; a1.w += w * h1v.w;
        }
        float4 h0 = s_h1_4[n * 4 + half * 2];
        float4 h1v = s_h1_4[n * 4 + half * 2 + 1];
        float av[8]  = {a0.x, a0.y, a0.z, a0.w, a1.x, a1.y, a1.z, a1.w};
        float hv[8]  = {h0.x, h0.y, h0.z, h0.w, h1v.x, h1v.y, h1v.z, h1v.w};

        unsigned long long acc0 = (half == 0) ? pk2(b2s[0], b2s[1]) : 0ULL;
        unsigned long long acc1 = (half == 0) ? pk2(b2s[2], b2s[3]) : 0ULL;
        #pragma unroll
        for (int f = 0; f < 8; f++) {
            const int row = half * 8 + f;
            ulonglong2 wr = *(const ulonglong2*)(w_rel2 + row * 4);
            ulonglong2 wo = *(const ulonglong2*)(w_root2 + row * 4);
            unsigned long long ad = pk2(av[f], av[f]);
            unsigned long long hd = pk2(hv[f], hv[f]);
            fma2(acc0, ad, wr.x); fma2(acc1, ad, wr.y);
            fma2(acc0, hd, wo.x); fma2(acc1, hd, wo.y);
        }
        unsigned m = __activemask();
        float2 v0 = upk(acc0), v1 = upk(acc1);
        float o0 = v0.x, o1 = v0.y, o2 = v1.x, o3 = v1.y;
        o0 = fmaxf(o0 + __shfl_xor_sync(m, o0, 1), 0.f);
        o1 = fmaxf(o1 + __shfl_xor_sync(m, o1, 1), 0.f);
        o2 = fmaxf(o2 + __shfl_xor_sync(m, o2, 1), 0.f);
        o3 = fmaxf(o3 + __shfl_xor_sync(m, o3, 1), 0.f);
        if (half == 0)
            *(float4*)(g_act + (size_t)g * ACTW + n * 4) = make_float4(o0, o1, o2, o3);
    }
}

// =================================================================
// K2: out = sigmoid(relu(act @ Wo1 + bo1) @ Wo2 + bo2)
// 64-row x 128-col tile per block (grid 512 x 128 thr), 8x8 thread tile,
// double-buffered smem. f32x2 packed FMAs; fused epilogue.
// =================================================================
__global__ __launch_bounds__(128)
void k2_outmlp(const float* __restrict__ Wo1,   // [226][128]
               const float* __restrict__ bo1,   // [128]
               const float* __restrict__ Wo2,   // [128]
               const float* __restrict__ bo2,   // [1]
               float* __restrict__ out)         // [B]
{
    __shared__ __align__(16) float sA[2][KCH * 64];    // [buf][kk*64 + row]
    __shared__ __align__(16) float sW[2][KCH * 128];   // [buf][kk*128 + col]
    const int tid = threadIdx.x;
    const int tx = tid & 15, ty = tid >> 4;
    const int blockRow = blockIdx.x * 64;
    const int r0 = ty * 8, c0 = tx * 8;

    unsigned long long acc[8][4];
    #pragma unroll
    for (int r = 0; r < 8; r++)
        #pragma unroll
        for (int cp = 0; cp < 4; cp++) acc[r][cp] = 0ULL;

    // chunk loader
    auto load_chunk = [&](int kb, int buf) {
        const int k0 = kb * KCH;
        #pragma unroll
        for (int q = 0; q < 2; q++) {                      // A: 64 rows x 16 k
            int idx = tid + q * 128;
            int row = idx & 63, kq = idx >> 6;
            float4 v = *(const float4*)(g_act + (size_t)(blockRow + row) * ACTW + k0 + kq * 4);
            sA[buf][(kq * 4 + 0) * 64 + row] = v.x;
            sA[buf][(kq * 4 + 1) * 64 + row] = v.y;
            sA[buf][(kq * 4 + 2) * 64 + row] = v.z;
            sA[buf][(kq * 4 + 3) * 64 + row] = v.w;
        }
        #pragma unroll
        for (int q = 0; q < 4; q++) {                      // W: 16 k x 128 cols
            int idx = tid + q * 128;
            int kk = idx >> 5, c4 = (idx & 31) * 4;
            int k = k0 + kk;
            float4 w = (k < 226) ? *(const float4*)(Wo1 + (size_t)k * 128 + c4)
                                 : make_float4(0.f, 0.f, 0.f, 0.f);
            *(float4*)(sW[buf] + kk * 128 + c4) = w;
        }
    };

    load_chunk(0, 0);
    __syncthreads();

    for (int kb = 0; kb < 15; kb++) {
        const int cur = kb & 1;
        if (kb < 14) load_chunk(kb + 1, cur ^ 1);
        #pragma unroll
        for (int kk = 0; kk < KCH; kk++) {
            float4 aLo = *(const float4*)(sA[cur] + kk * 64 + r0);
            float4 aHi = *(const float4*)(sA[cur] + kk * 64 + r0 + 4);
            ulonglong2 wA = *(const ulonglong2*)(sW[cur] + kk * 128 + c0);
            ulonglong2 wB = *(const ulonglong2*)(sW[cur] + kk * 128 + c0 + 4);
            float ar[8] = {aLo.x, aLo.y, aLo.z, aLo.w, aHi.x, aHi.y, aHi.z, aHi.w};
            #pragma unroll
            for (int r = 0; r < 8; r++) {
                unsigned long long ad = pk2(ar[r], ar[r]);
                fma2(acc[r][0], ad, wA.x);
                fma2(acc[r][1], ad, wA.y);
                fma2(acc[r][2], ad, wB.x);
                fma2(acc[r][3], ad, wB.y);
            }
        }
        __syncthreads();
    }

    // Epilogue: relu + dot with Wo2, reduce across 16 col-threads, sigmoid.
    float b1v[8], w2v[8];
    #pragma unroll
    for (int c = 0; c < 8; c++) { b1v[c] = bo1[c0 + c]; w2v[c] = Wo2[c0 + c]; }
    float p[8];
    #pragma unroll
    for (int r = 0; r < 8; r++) {
        p[r] = 0.f;
        #pragma unroll
        for (int cp = 0; cp < 4; cp++) {
            float2 v = upk(acc[r][cp]);
            p[r] += fmaxf(v.x + b1v[2 * cp],     0.f) * w2v[2 * cp];
            p[r] += fmaxf(v.y + b1v[2 * cp + 1], 0.f) * w2v[2 * cp + 1];
        }
    }
    #pragma unroll
    for (int r = 0; r < 8; r++) {
        #pragma unroll
        for (int off = 8; off > 0; off >>= 1)
            p[r] += __shfl_xor_sync(0xffffffffu, p[r], off, 16);
    }
    if (tx == 0) {
        float bb = bo2[0];
        #pragma unroll
        for (int r = 0; r < 8; r++) {
            float z = p[r] + bb;
            out[blockRow + r0 + r] = 1.f / (1.f + expf(-z));
        }
    }
}

extern "C" void kernel_launch(void* const* d_in, const int* in_sizes, int n_in,
                              void* d_out, int out_size)
{
    const float* x       = (const float*)d_in[0];
    const int*   ei      = (const int*)  d_in[1];
    const float* ea      = (const float*)d_in[2];
    const float* gf      = (const float*)d_in[3];
    const float* W_rel1  = (const float*)d_in[4];
    const float* b1      = (const float*)d_in[5];
    const float* W_root1 = (const float*)d_in[6];
    const float* W_rel2  = (const float*)d_in[7];
    const float* b2      = (const float*)d_in[8];
    const float* W_root2 = (const float*)d_in[9];
    const float* Wg1     = (const float*)d_in[10];
    const float* bg1     = (const float*)d_in[11];
    const float* Wg2     = (const float*)d_in[12];
    const float* bg2     = (const float*)d_in[13];
    const float* Wg3     = (const float*)d_in[14];
    const float* bg3     = (const float*)d_in[15];
    const float* Wo1     = (const float*)d_in[16];
    const float* bo1     = (const float*)d_in[17];
    const float* Wo2     = (const float*)d_in[18];
    const float* bo2     = (const float*)d_in[19];
    float* out = (float*)d_out;

    k1_graph<<<BGR, 128>>>(x, ei, ea, gf,
                           W_rel1, b1, W_root1,
                           W_rel2, b2, W_root2,
                           Wg1, bg1, Wg2, bg2, Wg3, bg3);
    k2_outmlp<<<BGR / 64, 128>>>(Wo1, bo1, Wo2, bo2, out);
}

// round 8
// speedup vs baseline: 1.3458x; 1.1482x over previous
#include <cuda_runtime.h>
#include <cuda_bf16.h>
#include <cstdint>
#include <math.h>

// Problem constants
#define BGR   32768      // graphs
#define NPG   54         // nodes per graph
#define EPG   144        // directed edges per graph
#define GLOB  10
#define ACTW  240        // padded activation width (216 embeds + 10 glob + 14 pad) = 15*16
#define KCH   16         // K-chunk for K2

// Scratch: concatenated activations [BGR][ACTW]; cols 226..239 zeroed
__device__ float g_act[(size_t)BGR * ACTW];

// ---------------- f32x2 packed helpers (sm_100+) ----------------
__device__ __forceinline__ unsigned long long pk2(float x, float y) {
    unsigned long long r;
    asm("mov.b64 %0, {%1, %2};" : "=l"(r) : "f"(x), "f"(y));
    return r;
}
__device__ __forceinline__ void fma2(unsigned long long &d, unsigned long long a, unsigned long long b) {
    asm("fma.rn.f32x2 %0, %1, %2, %0;" : "+l"(d) : "l"(a), "l"(b));
}
__device__ __forceinline__ float2 upk(unsigned long long v) {
    float2 f;
    asm("mov.b64 {%0, %1}, %2;" : "=f"(f.x), "=f"(f.y) : "l"(v));
    return f;
}

// =================================================================
// K1: per-graph fused GraphConv x2 + global MLP -> g_act
// Block-per-graph, phase-based (known-good R4 structure).
// Only change vs R4: CSR edge stream packed as float2 {attr, src}.
// =================================================================
__global__ __launch_bounds__(128)
void k1_graph(const float* __restrict__ x,
              const int*   __restrict__ ei,      // [2][E]
              const float* __restrict__ ea,      // [E]
              const float* __restrict__ gf,      // [B][10]
              const float* __restrict__ W_rel1,  // [8][16]
              const float* __restrict__ b1,      // [16]
              const float* __restrict__ W_root1, // [8][16]
              const float* __restrict__ W_rel2,  // [16][4]
              const float* __restrict__ b2,      // [4]
              const float* __restrict__ W_root2, // [16][4]
              const float* __restrict__ Wg1, const float* __restrict__ bg1,
              const float* __restrict__ Wg2, const float* __restrict__ bg2,
              const float* __restrict__ Wg3, const float* __restrict__ bg3)
{
    __shared__ float4 sx4[NPG * 2];          // x rows [54][8]
    __shared__ int    s_src[EPG], s_dst[EPG];
    __shared__ float  s_attr[EPG];
    __shared__ int    s_cnt[56], s_start[56], s_rank[EPG];
    __shared__ __align__(8) float2 s_sedge[EPG];   // sorted {attr, src_as_float}
    __shared__ float4 s_agg4[NPG * 2];       // conv1 aggregation [54][8]
    __shared__ float4 s_h1_4[NPG * 4];       // h1 [54][16]
    __shared__ float4 s_agg2_4[NPG * 4];     // conv2 aggregation [54][16]
    __shared__ float  w_rel1[128], w_root1[128], b1s[16];
    __shared__ float  w_rel2[64],  w_root2[64], b2s[4];
    __shared__ float  swg1[80], sbg1[8], swg2[64], sbg2[8], swg3[80], sbg3[10];
    __shared__ float  s_gf[GLOB];

    const int t    = threadIdx.x;
    const int lane = t & 31;
    const int warp = t >> 5;
    const int g    = blockIdx.x;
    float* s_h1 = (float*)s_h1_4;

    const long long E = (long long)BGR * EPG;

    // ---------------- Phase 0: loads (vectorized) ----------------
    if (t < NPG * 2) sx4[t] = ((const float4*)(x + (size_t)g * (NPG * 8)))[t];
    {
        const int base = g * NPG;
        if (t < 36) {                       // src: 144 ints = 36 int4
            int4 v = ((const int4*)(ei + (size_t)g * EPG))[t];
            s_src[t * 4 + 0] = v.x - base;
            s_src[t * 4 + 1] = v.y - base;
            s_src[t * 4 + 2] = v.z - base;
            s_src[t * 4 + 3] = v.w - base;
        } else if (t < 72) {                // dst
            int i = t - 36;
            int4 v = ((const int4*)(ei + E + (size_t)g * EPG))[i];
            s_dst[i * 4 + 0] = v.x - base;
            s_dst[i * 4 + 1] = v.y - base;
            s_dst[i * 4 + 2] = v.z - base;
            s_dst[i * 4 + 3] = v.w - base;
        } else if (t < 108) {               // attr
            int i = t - 72;
            float4 v = ((const float4*)(ea + (size_t)g * EPG))[i];
            s_attr[i * 4 + 0] = v.x;
            s_attr[i * 4 + 1] = v.y;
            s_attr[i * 4 + 2] = v.z;
            s_attr[i * 4 + 3] = v.w;
        }
    }
    if (t < 128) { w_rel1[t] = W_rel1[t]; w_root1[t] = W_root1[t]; }
    if (t < 16)  b1s[t] = b1[t];
    if (t < 64)  { w_rel2[t] = W_rel2[t]; w_root2[t] = W_root2[t]; }
    if (t < 4)   b2s[t] = b2[t];
    if (t < 80)  { swg1[t] = Wg1[t]; swg3[t] = Wg3[t]; }
    if (t < 64)  swg2[t] = Wg2[t];
    if (t < 8)   { sbg1[t] = bg1[t]; sbg2[t] = bg2[t]; }
    if (t < 10)  { sbg3[t] = bg3[t]; s_gf[t] = gf[(size_t)g * GLOB + t]; }
    __syncthreads();

    // ---------------- Phase 1: warp0 = CSR build, warp3 = global MLP ----------------
    if (warp == 0) {
        for (int i = lane; i < 56; i += 32) s_cnt[i] = 0;
        __syncwarp();
        #pragma unroll
        for (int c = 0; c < 5; c++) {
            int e = c * 32 + lane;
            bool valid = (e < EPG);
            int d = valid ? s_dst[e] : 54;      // sentinel bucket (unused)
            unsigned mask = __match_any_sync(0xffffffffu, d);
            int leader = __ffs(mask) - 1;
            int rk = __popc(mask & ((1u << lane) - 1u));
            int basec = s_cnt[d];
            if (valid) s_rank[e] = basec + rk;
            __syncwarp();
            if (lane == leader) s_cnt[d] = basec + __popc(mask);
            __syncwarp();
        }
        // Warp-parallel exclusive prefix scan of s_cnt[0..53] -> s_start[0..54]
        {
            int v0 = (lane < NPG) ? s_cnt[lane] : 0;
            int v1 = (lane + 32 < NPG) ? s_cnt[lane + 32] : 0;
            int s0 = v0, s1 = v1;
            #pragma unroll
            for (int off = 1; off < 32; off <<= 1) {
                int n0 = __shfl_up_sync(0xffffffffu, s0, off);
                int n1 = __shfl_up_sync(0xffffffffu, s1, off);
                if (lane >= off) { s0 += n0; s1 += n1; }
            }
            int total0 = __shfl_sync(0xffffffffu, s0, 31);
            s_start[lane] = s0 - v0;
            if (lane + 32 <= NPG) s_start[lane + 32] = total0 + s1 - v1;
        }
        __syncwarp();
        #pragma unroll
        for (int c = 0; c < 5; c++) {
            int e = c * 32 + lane;
            if (e < EPG) {
                int slot = s_start[s_dst[e]] + s_rank[e];
                s_sedge[slot] = make_float2(s_attr[e], __int_as_float(s_src[e]));
            }
        }
    } else if (warp == 3) {
        // Global MLP 10 -> 8 -> 8 -> 10 (single warp, shuffle-broadcast)
        float g1 = 0.f;
        if (lane < 8) {
            float a = sbg1[lane];
            #pragma unroll
            for (int i = 0; i < GLOB; i++) a += s_gf[i] * swg1[i * 8 + lane];
            g1 = fmaxf(a, 0.f);
        }
        float a2 = (lane < 8) ? sbg2[lane] : 0.f;
        #pragma unroll
        for (int i = 0; i < 8; i++) {
            float v = __shfl_sync(0xffffffffu, g1, i);
            if (lane < 8) a2 += v * swg2[i * 8 + lane];
        }
        float g2 = fmaxf(a2, 0.f);
        float a3 = (lane < GLOB) ? sbg3[lane] : 0.f;
        #pragma unroll
        for (int i = 0; i < 8; i++) {
            float v = __shfl_sync(0xffffffffu, g2, i);
            if (lane < GLOB) a3 += v * swg3[i * GLOB + lane];
        }
        if (lane < GLOB) g_act[(size_t)g * ACTW + 216 + lane] = fmaxf(a3, 0.f);
        if (lane >= GLOB && lane < 24) g_act[(size_t)g * ACTW + 216 + lane] = 0.f; // pad 226..239
    }
    __syncthreads();

    // ---------------- Phase 2: conv1 aggregation (gather via CSR) ----------------
    if (t < NPG * 2) {
        int n = t >> 1, half = t & 1;
        float4 acc = make_float4(0.f, 0.f, 0.f, 0.f);
        int i0 = s_start[n], i1 = s_start[n + 1];
        for (int i = i0; i < i1; i++) {
            float2 e2 = s_sedge[i];
            int s = __float_as_int(e2.y);
            float w = e2.x;
            float4 xv = sx4[s * 2 + half];
            acc.x += w * xv.x; acc.y += w * xv.y; acc.z += w * xv.z; acc.w += w * xv.w;
        }
        s_agg4[n * 2 + half] = acc;
    }
    __syncthreads();

    // ---------------- Phase 3: conv1 linear: h1 = relu(agg@Wrel1 + b1 + x@Wroot1) ----------------
    {
        int k = t & 15, ng = t >> 4;
        float wr[8], wo[8];
        #pragma unroll
        for (int f = 0; f < 8; f++) { wr[f] = w_rel1[f * 16 + k]; wo[f] = w_root1[f * 16 + k]; }
        float bb = b1s[k];
        for (int n = ng; n < NPG; n += 8) {
            float4 A0 = s_agg4[n * 2], A1 = s_agg4[n * 2 + 1];
            float4 X0 = sx4[n * 2],   X1 = sx4[n * 2 + 1];
            float acc = bb;
            acc += A0.x * wr[0] + A0.y * wr[1] + A0.z * wr[2] + A0.w * wr[3];
            acc += A1.x * wr[4] + A1.y * wr[5] + A1.z * wr[6] + A1.w * wr[7];
            acc += X0.x * wo[0] + X0.y * wo[1] + X0.z * wo[2] + X0.w * wo[3];
            acc += X1.x * wo[4] + X1.y * wo[5] + X1.z * wo[6] + X1.w * wo[7];
            s_h1[n * 16 + k] = fmaxf(acc, 0.f);
        }
    }
    __syncthreads();

    // ---------------- Phase 4: conv2 aggregation ----------------
    if (t < NPG * 2) {
        int n = t >> 1, half = t & 1;
        float4 a0 = make_float4(0.f, 0.f, 0.f, 0.f);
        float4 a1 = make_float4(0.f, 0.f, 0.f, 0.f);
        int i0 = s_start[n], i1 = s_start[n + 1];
        for (int i = i0; i < i1; i++) {
            float2 e2 = s_sedge[i];
            int s = __float_as_int(e2.y);
            float w = e2.x;
            float4 h0  = s_h1_4[s * 4 + half * 2];
            float4 h1v = s_h1_4[s * 4 + half * 2 + 1];
            a0.x += w * h0.x;  a0.y += w * h0.y;  a0.z += w * h0.z;  a0.w += w * h0.w;
            a1.x += w * h1v.x; a1.y += w * h1v.y; a1.z += w * h1v.z; a1.w += w * h1v.w;
        }
        s_agg2_4[n * 4 + half * 2]     = a0;
        s_agg2_4[n * 4 + half * 2 + 1] = a1;
    }
    __syncthreads();

    // ---------------- Phase 5: conv2 linear + write embeds ----------------
    if (t < 108) {
        int k = t & 3;   // (t + rep*108) & 3 == t & 3 since 108 % 4 == 0
        float w2r[16], w2o[16];
        #pragma unroll
        for (int f = 0; f < 16; f++) { w2r[f] = w_rel2[f * 4 + k]; w2o[f] = w_root2[f * 4 + k]; }
        float bb = b2s[k];
        #pragma unroll
        for (int rep = 0; rep < 2; rep++) {
            int o = t + rep * 108;
            int n = o >> 2;
            float acc = bb;
            #pragma unroll
            for (int q = 0; q < 4; q++) {
                float4 G = s_agg2_4[n * 4 + q];
                float4 H = s_h1_4[n * 4 + q];
                acc += G.x * w2r[q * 4 + 0] + G.y * w2r[q * 4 + 1] + G.z * w2r[q * 4 + 2] + G.w * w2r[q * 4 + 3];
                acc += H.x * w2o[q * 4 + 0] + H.y * w2o[q * 4 + 1] + H.z * w2o[q * 4 + 2] + H.w * w2o[q * 4 + 3];
            }
            g_act[(size_t)g * ACTW + o] = fmaxf(acc, 0.f);
        }
    }
}

// =================================================================
// K2: out = sigmoid(relu(act @ Wo1 + bo1) @ Wo2 + bo2)
// 64-row x 128-col tile per block (grid 512 x 128 thr), 8x8 thread tile,
// double-buffered smem. f32x2 packed FMAs; fused epilogue. (R5, 63.3us)
// =================================================================
__global__ __launch_bounds__(128)
void k2_outmlp(const float* __restrict__ Wo1,   // [226][128]
               const float* __restrict__ bo1,   // [128]
               const float* __restrict__ Wo2,   // [128]
               const float* __restrict__ bo2,   // [1]
               float* __restrict__ out)         // [B]
{
    __shared__ __align__(16) float sA[2][KCH * 64];
    __shared__ __align__(16) float sW[2][KCH * 128];
    const int tid = threadIdx.x;
    const int tx = tid & 15, ty = tid >> 4;
    const int blockRow = blockIdx.x * 64;
    const int r0 = ty * 8, c0 = tx * 8;

    unsigned long long acc[8][4];
    #pragma unroll
    for (int r = 0; r < 8; r++)
        #pragma unroll
        for (int cp = 0; cp < 4; cp++) acc[r][cp] = 0ULL;

    auto load_chunk = [&](int kb, int buf) {
        const int k0 = kb * KCH;
        #pragma unroll
        for (int q = 0; q < 2; q++) {                      // A: 64 rows x 16 k
            int idx = tid + q * 128;
            int row = idx & 63, kq = idx >> 6;
            float4 v = *(const float4*)(g_act + (size_t)(blockRow + row) * ACTW + k0 + kq * 4);
            sA[buf][(kq * 4 + 0) * 64 + row] = v.x;
            sA[buf][(kq * 4 + 1) * 64 + row] = v.y;
            sA[buf][(kq * 4 + 2) * 64 + row] = v.z;
            sA[buf][(kq * 4 + 3) * 64 + row] = v.w;
        }
        #pragma unroll
        for (int q = 0; q < 4; q++) {                      // W: 16 k x 128 cols
            int idx = tid + q * 128;
            int kk = idx >> 5, c4 = (idx & 31) * 4;
            int k = k0 + kk;
            float4 w = (k < 226) ? *(const float4*)(Wo1 + (size_t)k * 128 + c4)
                                 : make_float4(0.f, 0.f, 0.f, 0.f);
            *(float4*)(sW[buf] + kk * 128 + c4) = w;
        }
    };

    load_chunk(0, 0);
    __syncthreads();

    for (int kb = 0; kb < 15; kb++) {
        const int cur = kb & 1;
        if (kb < 14) load_chunk(kb + 1, cur ^ 1);
        #pragma unroll
        for (int kk = 0; kk < KCH; kk++) {
            float4 aLo = *(const float4*)(sA[cur] + kk * 64 + r0);
            float4 aHi = *(const float4*)(sA[cur] + kk * 64 + r0 + 4);
            ulonglong2 wA = *(const ulonglong2*)(sW[cur] + kk * 128 + c0);
            ulonglong2 wB = *(const ulonglong2*)(sW[cur] + kk * 128 + c0 + 4);
            float ar[8] = {aLo.x, aLo.y, aLo.z, aLo.w, aHi.x, aHi.y, aHi.z, aHi.w};
            #pragma unroll
            for (int r = 0; r < 8; r++) {
                unsigned long long ad = pk2(ar[r], ar[r]);
                fma2(acc[r][0], ad, wA.x);
                fma2(acc[r][1], ad, wA.y);
                fma2(acc[r][2], ad, wB.x);
                fma2(acc[r][3], ad, wB.y);
            }
        }
        __syncthreads();
    }

    // Epilogue: relu + dot with Wo2, reduce across 16 col-threads, sigmoid.
    float b1v[8], w2v[8];
    #pragma unroll
    for (int c = 0; c < 8; c++) { b1v[c] = bo1[c0 + c]; w2v[c] = Wo2[c0 + c]; }
    float p[8];
    #pragma unroll
    for (int r = 0; r < 8; r++) {
        p[r] = 0.f;
        #pragma unroll
        for (int cp = 0; cp < 4; cp++) {
            float2 v = upk(acc[r][cp]);
            p[r] += fmaxf(v.x + b1v[2 * cp],     0.f) * w2v[2 * cp];
            p[r] += fmaxf(v.y + b1v[2 * cp + 1], 0.f) * w2v[2 * cp + 1];
        }
    }
    #pragma unroll
    for (int r = 0; r < 8; r++) {
        #pragma unroll
        for (int off = 8; off > 0; off >>= 1)
            p[r] += __shfl_xor_sync(0xffffffffu, p[r], off, 16);
    }
    if (tx == 0) {
        float bb = bo2[0];
        #pragma unroll
        for (int r = 0; r < 8; r++) {
            float z = p[r] + bb;
            out[blockRow + r0 + r] = 1.f / (1.f + expf(-z));
        }
    }
}

extern "C" void kernel_launch(void* const* d_in, const int* in_sizes, int n_in,
                              void* d_out, int out_size)
{
    const float* x       = (const float*)d_in[0];
    const int*   ei      = (const int*)  d_in[1];
    const float* ea      = (const float*)d_in[2];
    const float* gf      = (const float*)d_in[3];
    const float* W_rel1  = (const float*)d_in[4];
    const float* b1      = (const float*)d_in[5];
    const float* W_root1 = (const float*)d_in[6];
    const float* W_rel2  = (const float*)d_in[7];
    const float* b2      = (const float*)d_in[8];
    const float* W_root2 = (const float*)d_in[9];
    const float* Wg1     = (const float*)d_in[10];
    const float* bg1     = (const float*)d_in[11];
    const float* Wg2     = (const float*)d_in[12];
    const float* bg2     = (const float*)d_in[13];
    const float* Wg3     = (const float*)d_in[14];
    const float* bg3     = (const float*)d_in[15];
    const float* Wo1     = (const float*)d_in[16];
    const float* bo1     = (const float*)d_in[17];
    const float* Wo2     = (const float*)d_in[18];
    const float* bo2     = (const float*)d_in[19];
    float* out = (float*)d_out;

    k1_graph<<<BGR, 128>>>(x, ei, ea, gf,
                           W_rel1, b1, W_root1,
                           W_rel2, b2, W_root2,
                           Wg1, bg1, Wg2, bg2, Wg3, bg3);
    k2_outmlp<<<BGR / 64, 128>>>(Wo1, bo1, Wo2, bo2, out);
}

// round 9
// speedup vs baseline: 1.5142x; 1.1252x over previous
#include <cuda_runtime.h>
#include <cuda_bf16.h>
#include <cstdint>
#include <math.h>

// Problem constants
#define BGR   32768      // graphs
#define NPG   54         // nodes per graph
#define EPG   144        // directed edges per graph
#define GLOB  10
#define ACTW  240        // padded activation width (216 embeds + 10 glob + 14 pad) = 15*16
#define KCH   16         // K-chunk for K2

// Scratch: concatenated activations [BGR][ACTW]; cols 226..239 zeroed
__device__ float g_act[(size_t)BGR * ACTW];

// ---------------- f32x2 packed helpers (sm_100+) ----------------
__device__ __forceinline__ unsigned long long pk2(float x, float y) {
    unsigned long long r;
    asm("mov.b64 %0, {%1, %2};" : "=l"(r) : "f"(x), "f"(y));
    return r;
}
__device__ __forceinline__ void fma2(unsigned long long &d, unsigned long long a, unsigned long long b) {
    asm("fma.rn.f32x2 %0, %1, %2, %0;" : "+l"(d) : "l"(a), "l"(b));
}
__device__ __forceinline__ float2 upk(unsigned long long v) {
    float2 f;
    asm("mov.b64 {%0, %1}, %2;" : "=f"(f.x), "=f"(f.y) : "l"(v));
    return f;
}

// =================================================================
// K1: per-graph fused GraphConv x2 + global MLP -> g_act
// Block-per-graph, phase-based. vs R8:
//  - P1: warps 1-2 precompute y_root = x@W_root1 + b1
//  - conv2 uses transform-then-aggregate (z = h1@W2 first, then 4-wide gather)
//  - old P5 folded into P4 (writes g_act directly)
// =================================================================
__global__ __launch_bounds__(128)
void k1_graph(const float* __restrict__ x,
              const int*   __restrict__ ei,      // [2][E]
              const float* __restrict__ ea,      // [E]
              const float* __restrict__ gf,      // [B][10]
              const float* __restrict__ W_rel1,  // [8][16]
              const float* __restrict__ b1,      // [16]
              const float* __restrict__ W_root1, // [8][16]
              const float* __restrict__ W_rel2,  // [16][4]
              const float* __restrict__ b2,      // [4]
              const float* __restrict__ W_root2, // [16][4]
              const float* __restrict__ Wg1, const float* __restrict__ bg1,
              const float* __restrict__ Wg2, const float* __restrict__ bg2,
              const float* __restrict__ Wg3, const float* __restrict__ bg3)
{
    __shared__ float4 sx4[NPG * 2];          // x rows [54][8]
    __shared__ int    s_src[EPG], s_dst[EPG];
    __shared__ float  s_attr[EPG];
    __shared__ int    s_cnt[56], s_start[56], s_rank[EPG];
    __shared__ __align__(8) float2 s_sedge[EPG];   // sorted {attr, src_as_float}
    __shared__ float4 s_agg4[NPG * 2];       // conv1 aggregation [54][8]
    __shared__ __align__(8) float s_yroot[NPG * 16];   // x@W_root1 + b1
    __shared__ float4 s_h1_4[NPG * 4];       // h1 [54][16]
    __shared__ __align__(16) float4 s_zrel[NPG];    // h1@W_rel2
    __shared__ __align__(16) float4 s_zroot[NPG];   // h1@W_root2 + b2
    __shared__ __align__(16) float  w_rel1[128], w_root1[128], b1s[16];
    __shared__ __align__(16) float  w_rel2[64],  w_root2[64], b2s[4];
    __shared__ float  swg1[80], sbg1[8], swg2[64], sbg2[8], swg3[80], sbg3[10];
    __shared__ float  s_gf[GLOB];

    const int t    = threadIdx.x;
    const int lane = t & 31;
    const int warp = t >> 5;
    const int g    = blockIdx.x;
    float* s_h1 = (float*)s_h1_4;

    const long long E = (long long)BGR * EPG;

    // ---------------- Phase 0: loads (vectorized) ----------------
    if (t < NPG * 2) sx4[t] = ((const float4*)(x + (size_t)g * (NPG * 8)))[t];
    {
        const int base = g * NPG;
        if (t < 36) {                       // src: 144 ints = 36 int4
            int4 v = ((const int4*)(ei + (size_t)g * EPG))[t];
            s_src[t * 4 + 0] = v.x - base;
            s_src[t * 4 + 1] = v.y - base;
            s_src[t * 4 + 2] = v.z - base;
            s_src[t * 4 + 3] = v.w - base;
        } else if (t < 72) {                // dst
            int i = t - 36;
            int4 v = ((const int4*)(ei + E + (size_t)g * EPG))[i];
            s_dst[i * 4 + 0] = v.x - base;
            s_dst[i * 4 + 1] = v.y - base;
            s_dst[i * 4 + 2] = v.z - base;
            s_dst[i * 4 + 3] = v.w - base;
        } else if (t < 108) {               // attr
            int i = t - 72;
            float4 v = ((const float4*)(ea + (size_t)g * EPG))[i];
            s_attr[i * 4 + 0] = v.x;
            s_attr[i * 4 + 1] = v.y;
            s_attr[i * 4 + 2] = v.z;
            s_attr[i * 4 + 3] = v.w;
        }
    }
    if (t < 128) { w_rel1[t] = W_rel1[t]; w_root1[t] = W_root1[t]; }
    if (t < 16)  b1s[t] = b1[t];
    if (t < 64)  { w_rel2[t] = W_rel2[t]; w_root2[t] = W_root2[t]; }
    if (t < 4)   b2s[t] = b2[t];
    if (t < 80)  { swg1[t] = Wg1[t]; swg3[t] = Wg3[t]; }
    if (t < 64)  swg2[t] = Wg2[t];
    if (t < 8)   { sbg1[t] = bg1[t]; sbg2[t] = bg2[t]; }
    if (t < 10)  { sbg3[t] = bg3[t]; s_gf[t] = gf[(size_t)g * GLOB + t]; }
    __syncthreads();

    // ---------------- Phase 1: warp0 = CSR, warps1-2 = y_root, warp3 = MLP ----------------
    if (warp == 0) {
        for (int i = lane; i < 56; i += 32) s_cnt[i] = 0;
        __syncwarp();
        #pragma unroll
        for (int c = 0; c < 5; c++) {
            int e = c * 32 + lane;
            bool valid = (e < EPG);
            int d = valid ? s_dst[e] : 54;      // sentinel bucket (unused)
            unsigned mask = __match_any_sync(0xffffffffu, d);
            int leader = __ffs(mask) - 1;
            int rk = __popc(mask & ((1u << lane) - 1u));
            int basec = s_cnt[d];
            if (valid) s_rank[e] = basec + rk;
            __syncwarp();
            if (lane == leader) s_cnt[d] = basec + __popc(mask);
            __syncwarp();
        }
        // Warp-parallel exclusive prefix scan of s_cnt[0..53] -> s_start[0..54]
        {
            int v0 = (lane < NPG) ? s_cnt[lane] : 0;
            int v1 = (lane + 32 < NPG) ? s_cnt[lane + 32] : 0;
            int s0 = v0, s1 = v1;
            #pragma unroll
            for (int off = 1; off < 32; off <<= 1) {
                int n0 = __shfl_up_sync(0xffffffffu, s0, off);
                int n1 = __shfl_up_sync(0xffffffffu, s1, off);
                if (lane >= off) { s0 += n0; s1 += n1; }
            }
            int total0 = __shfl_sync(0xffffffffu, s0, 31);
            s_start[lane] = s0 - v0;
            if (lane + 32 <= NPG) s_start[lane + 32] = total0 + s1 - v1;
        }
        __syncwarp();
        #pragma unroll
        for (int c = 0; c < 5; c++) {
            int e = c * 32 + lane;
            if (e < EPG) {
                int slot = s_start[s_dst[e]] + s_rank[e];
                s_sedge[slot] = make_float2(s_attr[e], __int_as_float(s_src[e]));
            }
        }
    } else if (warp == 3) {
        // Global MLP 10 -> 8 -> 8 -> 10 (single warp, shuffle-broadcast)
        float g1 = 0.f;
        if (lane < 8) {
            float a = sbg1[lane];
            #pragma unroll
            for (int i = 0; i < GLOB; i++) a += s_gf[i] * swg1[i * 8 + lane];
            g1 = fmaxf(a, 0.f);
        }
        float a2 = (lane < 8) ? sbg2[lane] : 0.f;
        #pragma unroll
        for (int i = 0; i < 8; i++) {
            float v = __shfl_sync(0xffffffffu, g1, i);
            if (lane < 8) a2 += v * swg2[i * 8 + lane];
        }
        float g2 = fmaxf(a2, 0.f);
        float a3 = (lane < GLOB) ? sbg3[lane] : 0.f;
        #pragma unroll
        for (int i = 0; i < 8; i++) {
            float v = __shfl_sync(0xffffffffu, g2, i);
            if (lane < GLOB) a3 += v * swg3[i * GLOB + lane];
        }
        if (lane < GLOB) g_act[(size_t)g * ACTW + 216 + lane] = fmaxf(a3, 0.f);
        if (lane >= GLOB && lane < 24) g_act[(size_t)g * ACTW + 216 + lane] = 0.f; // pad 226..239
    } else {
        // warps 1-2: y_root[n][k-pair] = x[n] @ W_root1 + b1 (f32x2 pairs)
        int idx = (warp - 1) * 32 + lane;                 // 0..63
        for (int o = idx; o < NPG * 8; o += 64) {         // 432 float2 outputs
            int n = o >> 3, j = o & 7;                    // node, k-pair
            float4 X0 = sx4[n * 2], X1 = sx4[n * 2 + 1];
            float xf[8] = {X0.x, X0.y, X0.z, X0.w, X1.x, X1.y, X1.z, X1.w};
            unsigned long long acc = *(const unsigned long long*)(b1s + 2 * j);
            #pragma unroll
            for (int f = 0; f < 8; f++) {
                unsigned long long wd = *(const unsigned long long*)(w_root1 + f * 16 + 2 * j);
                fma2(acc, pk2(xf[f], xf[f]), wd);
            }
            *(float2*)(s_yroot + n * 16 + 2 * j) = upk(acc);
        }
    }
    __syncthreads();

    // ---------------- Phase 2: conv1 aggregation (gather via CSR) ----------------
    if (t < NPG * 2) {
        int n = t >> 1, half = t & 1;
        float4 acc = make_float4(0.f, 0.f, 0.f, 0.f);
        int i0 = s_start[n], i1 = s_start[n + 1];
        for (int i = i0; i < i1; i++) {
            float2 e2 = s_sedge[i];
            int s = __float_as_int(e2.y);
            float w = e2.x;
            float4 xv = sx4[s * 2 + half];
            acc.x += w * xv.x; acc.y += w * xv.y; acc.z += w * xv.z; acc.w += w * xv.w;
        }
        s_agg4[n * 2 + half] = acc;
    }
    __syncthreads();

    // ---------------- Phase 3: conv1 linear: h1 = relu(agg@Wrel1 + y_root) ----------------
    {
        int k = t & 15, ng = t >> 4;
        float wr[8];
        #pragma unroll
        for (int f = 0; f < 8; f++) wr[f] = w_rel1[f * 16 + k];
        for (int n = ng; n < NPG; n += 8) {
            float4 A0 = s_agg4[n * 2], A1 = s_agg4[n * 2 + 1];
            float acc = s_yroot[n * 16 + k];
            acc += A0.x * wr[0] + A0.y * wr[1] + A0.z * wr[2] + A0.w * wr[3];
            acc += A1.x * wr[4] + A1.y * wr[5] + A1.z * wr[6] + A1.w * wr[7];
            s_h1[n * 16 + k] = fmaxf(acc, 0.f);
        }
    }
    __syncthreads();

    // ---------------- Phase 3b: z_rel = h1@W_rel2, z_root = h1@W_root2 + b2 ----------------
    if (t < NPG * 2) {
        int n = t >> 1, half = t & 1;
        const float* W = half ? w_root2 : w_rel2;     // [16][4]
        float4 H0 = s_h1_4[n * 4 + 0];
        float4 H1 = s_h1_4[n * 4 + 1];
        float4 H2 = s_h1_4[n * 4 + 2];
        float4 H3 = s_h1_4[n * 4 + 3];
        float hv[16] = {H0.x, H0.y, H0.z, H0.w, H1.x, H1.y, H1.z, H1.w,
                        H2.x, H2.y, H2.z, H2.w, H3.x, H3.y, H3.z, H3.w};
        unsigned long long acc0 = 0ULL, acc1 = 0ULL;
        if (half) {
            ulonglong2 bb = *(const ulonglong2*)b2s;
            acc0 = bb.x; acc1 = bb.y;
        }
        #pragma unroll
        for (int f = 0; f < 16; f++) {
            ulonglong2 wd = *(const ulonglong2*)(W + f * 4);
            unsigned long long hd = pk2(hv[f], hv[f]);
            fma2(acc0, hd, wd.x);
            fma2(acc1, hd, wd.y);
        }
        float2 v0 = upk(acc0), v1 = upk(acc1);
        float4 z = make_float4(v0.x, v0.y, v1.x, v1.y);
        if (half) s_zroot[n] = z; else s_zrel[n] = z;
    }
    __syncthreads();

    // ---------------- Phase 4: conv2 aggregation (4-wide) + write g_act ----------------
    if (t < NPG * 2) {
        int n = t >> 1, half = t & 1;
        const float* zr = (const float*)s_zrel;
        float2 acc = *(const float2*)((const float*)(s_zroot + n) + half * 2);
        int i0 = s_start[n], i1 = s_start[n + 1];
        for (int i = i0; i < i1; i++) {
            float2 e2 = s_sedge[i];
            int s = __float_as_int(e2.y);
            float w = e2.x;
            float2 z = *(const float2*)(zr + s * 4 + half * 2);
            acc.x += w * z.x;
            acc.y += w * z.y;
        }
        *(float2*)(g_act + (size_t)g * ACTW + n * 4 + half * 2) =
            make_float2(fmaxf(acc.x, 0.f), fmaxf(acc.y, 0.f));
    }
}

// =================================================================
// K2: out = sigmoid(relu(act @ Wo1 + bo1) @ Wo2 + bo2)
// 64-row x 128-col tile per block (grid 512 x 128 thr), 8x8 thread tile,
// double-buffered smem. f32x2 packed FMAs; fused epilogue. (R5/R8, 58.6us)
// =================================================================
__global__ __launch_bounds__(128)
void k2_outmlp(const float* __restrict__ Wo1,   // [226][128]
               const float* __restrict__ bo1,   // [128]
               const float* __restrict__ Wo2,   // [128]
               const float* __restrict__ bo2,   // [1]
               float* __restrict__ out)         // [B]
{
    __shared__ __align__(16) float sA[2][KCH * 64];
    __shared__ __align__(16) float sW[2][KCH * 128];
    const int tid = threadIdx.x;
    const int tx = tid & 15, ty = tid >> 4;
    const int blockRow = blockIdx.x * 64;
    const int r0 = ty * 8, c0 = tx * 8;

    unsigned long long acc[8][4];
    #pragma unroll
    for (int r = 0; r < 8; r++)
        #pragma unroll
        for (int cp = 0; cp < 4; cp++) acc[r][cp] = 0ULL;

    auto load_chunk = [&](int kb, int buf) {
        const int k0 = kb * KCH;
        #pragma unroll
        for (int q = 0; q < 2; q++) {                      // A: 64 rows x 16 k
            int idx = tid + q * 128;
            int row = idx & 63, kq = idx >> 6;
            float4 v = *(const float4*)(g_act + (size_t)(blockRow + row) * ACTW + k0 + kq * 4);
            sA[buf][(kq * 4 + 0) * 64 + row] = v.x;
            sA[buf][(kq * 4 + 1) * 64 + row] = v.y;
            sA[buf][(kq * 4 + 2) * 64 + row] = v.z;
            sA[buf][(kq * 4 + 3) * 64 + row] = v.w;
        }
        #pragma unroll
        for (int q = 0; q < 4; q++) {                      // W: 16 k x 128 cols
            int idx = tid + q * 128;
            int kk = idx >> 5, c4 = (idx & 31) * 4;
            int k = k0 + kk;
            float4 w = (k < 226) ? *(const float4*)(Wo1 + (size_t)k * 128 + c4)
                                 : make_float4(0.f, 0.f, 0.f, 0.f);
            *(float4*)(sW[buf] + kk * 128 + c4) = w;
        }
    };

    load_chunk(0, 0);
    __syncthreads();

    for (int kb = 0; kb < 15; kb++) {
        const int cur = kb & 1;
        if (kb < 14) load_chunk(kb + 1, cur ^ 1);
        #pragma unroll
        for (int kk = 0; kk < KCH; kk++) {
            float4 aLo = *(const float4*)(sA[cur] + kk * 64 + r0);
            float4 aHi = *(const float4*)(sA[cur] + kk * 64 + r0 + 4);
            ulonglong2 wA = *(const ulonglong2*)(sW[cur] + kk * 128 + c0);
            ulonglong2 wB = *(const ulonglong2*)(sW[cur] + kk * 128 + c0 + 4);
            float ar[8] = {aLo.x, aLo.y, aLo.z, aLo.w, aHi.x, aHi.y, aHi.z, aHi.w};
            #pragma unroll
            for (int r = 0; r < 8; r++) {
                unsigned long long ad = pk2(ar[r], ar[r]);
                fma2(acc[r][0], ad, wA.x);
                fma2(acc[r][1], ad, wA.y);
                fma2(acc[r][2], ad, wB.x);
                fma2(acc[r][3], ad, wB.y);
            }
        }
        __syncthreads();
    }

    // Epilogue: relu + dot with Wo2, reduce across 16 col-threads, sigmoid.
    float b1v[8], w2v[8];
    #pragma unroll
    for (int c = 0; c < 8; c++) { b1v[c] = bo1[c0 + c]; w2v[c] = Wo2[c0 + c]; }
    float p[8];
    #pragma unroll
    for (int r = 0; r < 8; r++) {
        p[r] = 0.f;
        #pragma unroll
        for (int cp = 0; cp < 4; cp++) {
            float2 v = upk(acc[r][cp]);
            p[r] += fmaxf(v.x + b1v[2 * cp],     0.f) * w2v[2 * cp];
            p[r] += fmaxf(v.y + b1v[2 * cp + 1], 0.f) * w2v[2 * cp + 1];
        }
    }
    #pragma unroll
    for (int r = 0; r < 8; r++) {
        #pragma unroll
        for (int off = 8; off > 0; off >>= 1)
            p[r] += __shfl_xor_sync(0xffffffffu, p[r], off, 16);
    }
    if (tx == 0) {
        float bb = bo2[0];
        #pragma unroll
        for (int r = 0; r < 8; r++) {
            float z = p[r] + bb;
            out[blockRow + r0 + r] = 1.f / (1.f + expf(-z));
        }
    }
}

extern "C" void kernel_launch(void* const* d_in, const int* in_sizes, int n_in,
                              void* d_out, int out_size)
{
    const float* x       = (const float*)d_in[0];
    const int*   ei      = (const int*)  d_in[1];
    const float* ea      = (const float*)d_in[2];
    const float* gf      = (const float*)d_in[3];
    const float* W_rel1  = (const float*)d_in[4];
    const float* b1      = (const float*)d_in[5];
    const float* W_root1 = (const float*)d_in[6];
    const float* W_rel2  = (const float*)d_in[7];
    const float* b2      = (const float*)d_in[8];
    const float* W_root2 = (const float*)d_in[9];
    const float* Wg1     = (const float*)d_in[10];
    const float* bg1     = (const float*)d_in[11];
    const float* Wg2     = (const float*)d_in[12];
    const float* bg2     = (const float*)d_in[13];
    const float* Wg3     = (const float*)d_in[14];
    const float* bg3     = (const float*)d_in[15];
    const float* Wo1     = (const float*)d_in[16];
    const float* bo1     = (const float*)d_in[17];
    const float* Wo2     = (const float*)d_in[18];
    const float* bo2     = (const float*)d_in[19];
    float* out = (float*)d_out;

    k1_graph<<<BGR, 128>>>(x, ei, ea, gf,
                           W_rel1, b1, W_root1,
                           W_rel2, b2, W_root2,
                           Wg1, bg1, Wg2, bg2, Wg3, bg3);
    k2_outmlp<<<BGR / 64, 128>>>(Wo1, bo1, Wo2, bo2, out);
}

// round 10
// speedup vs baseline: 1.5962x; 1.0541x over previous
#include <cuda_runtime.h>
#include <cuda_bf16.h>
#include <cstdint>
#include <math.h>

// Problem constants
#define BGR   32768      // graphs
#define NPG   54         // nodes per graph
#define EPG   144        // directed edges per graph
#define GLOB  10
#define ACTW  240        // padded activation width (216 embeds + 10 glob + 14 pad) = 15*16
#define KCH   16         // K-chunk for K2

// Scratch: concatenated activations [BGR][ACTW]; cols 226..239 zeroed
__device__ float g_act[(size_t)BGR * ACTW];

// ---------------- f32x2 packed helpers (sm_100+) ----------------
__device__ __forceinline__ unsigned long long pk2(float x, float y) {
    unsigned long long r;
    asm("mov.b64 %0, {%1, %2};" : "=l"(r) : "f"(x), "f"(y));
    return r;
}
__device__ __forceinline__ void fma2(unsigned long long &d, unsigned long long a, unsigned long long b) {
    asm("fma.rn.f32x2 %0, %1, %2, %0;" : "+l"(d) : "l"(a), "l"(b));
}
__device__ __forceinline__ float2 upk(unsigned long long v) {
    float2 f;
    asm("mov.b64 {%0, %1}, %2;" : "=f"(f.x), "=f"(f.y) : "l"(v));
    return f;
}

// =================================================================
// K1: per-graph fused GraphConv x2 + global MLP -> g_act
// Block-per-graph. 3 barriers. vs R9: P2+P3+P3b fused into one phase —
// agg -> h1 -> z stays in the register pair (2n, 2n+1), stitched by
// shfl_xor(1). h1/agg never touch smem.
// =================================================================
__global__ __launch_bounds__(128)
void k1_graph(const float* __restrict__ x,
              const int*   __restrict__ ei,      // [2][E]
              const float* __restrict__ ea,      // [E]
              const float* __restrict__ gf,      // [B][10]
              const float* __restrict__ W_rel1,  // [8][16]
              const float* __restrict__ b1,      // [16]
              const float* __restrict__ W_root1, // [8][16]
              const float* __restrict__ W_rel2,  // [16][4]
              const float* __restrict__ b2,      // [4]
              const float* __restrict__ W_root2, // [16][4]
              const float* __restrict__ Wg1, const float* __restrict__ bg1,
              const float* __restrict__ Wg2, const float* __restrict__ bg2,
              const float* __restrict__ Wg3, const float* __restrict__ bg3)
{
    __shared__ float4 sx4[NPG * 2];          // x rows [54][8]
    __shared__ int    s_src[EPG], s_dst[EPG];
    __shared__ float  s_attr[EPG];
    __shared__ int    s_cnt[56], s_start[56], s_rank[EPG];
    __shared__ __align__(8) float2 s_sedge[EPG];   // sorted {attr, src_as_float}
    __shared__ __align__(8) float s_yroot[NPG * 16];   // x@W_root1 + b1
    __shared__ __align__(16) float4 s_zrel[NPG];    // h1@W_rel2
    __shared__ __align__(16) float4 s_zroot[NPG];   // h1@W_root2 + b2
    __shared__ __align__(16) float  w_rel1[128], w_root1[128], b1s[16];
    __shared__ __align__(16) float  w_rel2[64],  w_root2[64], b2s[4];
    __shared__ float  swg1[80], sbg1[8], swg2[64], sbg2[8], swg3[80], sbg3[10];
    __shared__ float  s_gf[GLOB];

    const int t    = threadIdx.x;
    const int lane = t & 31;
    const int warp = t >> 5;
    const int g    = blockIdx.x;

    const long long E = (long long)BGR * EPG;

    // ---------------- Phase 0: loads (vectorized) ----------------
    if (t < NPG * 2) sx4[t] = ((const float4*)(x + (size_t)g * (NPG * 8)))[t];
    {
        const int base = g * NPG;
        if (t < 36) {                       // src: 144 ints = 36 int4
            int4 v = ((const int4*)(ei + (size_t)g * EPG))[t];
            s_src[t * 4 + 0] = v.x - base;
            s_src[t * 4 + 1] = v.y - base;
            s_src[t * 4 + 2] = v.z - base;
            s_src[t * 4 + 3] = v.w - base;
        } else if (t < 72) {                // dst
            int i = t - 36;
            int4 v = ((const int4*)(ei + E + (size_t)g * EPG))[i];
            s_dst[i * 4 + 0] = v.x - base;
            s_dst[i * 4 + 1] = v.y - base;
            s_dst[i * 4 + 2] = v.z - base;
            s_dst[i * 4 + 3] = v.w - base;
        } else if (t < 108) {               // attr
            int i = t - 72;
            float4 v = ((const float4*)(ea + (size_t)g * EPG))[i];
            s_attr[i * 4 + 0] = v.x;
            s_attr[i * 4 + 1] = v.y;
            s_attr[i * 4 + 2] = v.z;
            s_attr[i * 4 + 3] = v.w;
        }
    }
    if (t < 128) { w_rel1[t] = W_rel1[t]; w_root1[t] = W_root1[t]; }
    if (t < 16)  b1s[t] = b1[t];
    if (t < 64)  { w_rel2[t] = W_rel2[t]; w_root2[t] = W_root2[t]; }
    if (t < 4)   b2s[t] = b2[t];
    if (t < 80)  { swg1[t] = Wg1[t]; swg3[t] = Wg3[t]; }
    if (t < 64)  swg2[t] = Wg2[t];
    if (t < 8)   { sbg1[t] = bg1[t]; sbg2[t] = bg2[t]; }
    if (t < 10)  { sbg3[t] = bg3[t]; s_gf[t] = gf[(size_t)g * GLOB + t]; }
    __syncthreads();

    // ---------------- Phase 1: warp0 = CSR, warps1-2 = y_root, warp3 = MLP ----------------
    if (warp == 0) {
        for (int i = lane; i < 56; i += 32) s_cnt[i] = 0;
        __syncwarp();
        #pragma unroll
        for (int c = 0; c < 5; c++) {
            int e = c * 32 + lane;
            bool valid = (e < EPG);
            int d = valid ? s_dst[e] : 54;      // sentinel bucket (unused)
            unsigned mask = __match_any_sync(0xffffffffu, d);
            int leader = __ffs(mask) - 1;
            int rk = __popc(mask & ((1u << lane) - 1u));
            int basec = s_cnt[d];
            if (valid) s_rank[e] = basec + rk;
            __syncwarp();
            if (lane == leader) s_cnt[d] = basec + __popc(mask);
            __syncwarp();
        }
        // Warp-parallel exclusive prefix scan of s_cnt[0..53] -> s_start[0..54]
        {
            int v0 = (lane < NPG) ? s_cnt[lane] : 0;
            int v1 = (lane + 32 < NPG) ? s_cnt[lane + 32] : 0;
            int s0 = v0, s1 = v1;
            #pragma unroll
            for (int off = 1; off < 32; off <<= 1) {
                int n0 = __shfl_up_sync(0xffffffffu, s0, off);
                int n1 = __shfl_up_sync(0xffffffffu, s1, off);
                if (lane >= off) { s0 += n0; s1 += n1; }
            }
            int total0 = __shfl_sync(0xffffffffu, s0, 31);
            s_start[lane] = s0 - v0;
            if (lane + 32 <= NPG) s_start[lane + 32] = total0 + s1 - v1;
        }
        __syncwarp();
        #pragma unroll
        for (int c = 0; c < 5; c++) {
            int e = c * 32 + lane;
            if (e < EPG) {
                int slot = s_start[s_dst[e]] + s_rank[e];
                s_sedge[slot] = make_float2(s_attr[e], __int_as_float(s_src[e]));
            }
        }
    } else if (warp == 3) {
        // Global MLP 10 -> 8 -> 8 -> 10 (single warp, shuffle-broadcast)
        float g1 = 0.f;
        if (lane < 8) {
            float a = sbg1[lane];
            #pragma unroll
            for (int i = 0; i < GLOB; i++) a += s_gf[i] * swg1[i * 8 + lane];
            g1 = fmaxf(a, 0.f);
        }
        float a2 = (lane < 8) ? sbg2[lane] : 0.f;
        #pragma unroll
        for (int i = 0; i < 8; i++) {
            float v = __shfl_sync(0xffffffffu, g1, i);
            if (lane < 8) a2 += v * swg2[i * 8 + lane];
        }
        float g2 = fmaxf(a2, 0.f);
        float a3 = (lane < GLOB) ? sbg3[lane] : 0.f;
        #pragma unroll
        for (int i = 0; i < 8; i++) {
            float v = __shfl_sync(0xffffffffu, g2, i);
            if (lane < GLOB) a3 += v * swg3[i * GLOB + lane];
        }
        if (lane < GLOB) g_act[(size_t)g * ACTW + 216 + lane] = fmaxf(a3, 0.f);
        if (lane >= GLOB && lane < 24) g_act[(size_t)g * ACTW + 216 + lane] = 0.f; // pad 226..239
    } else {
        // warps 1-2: y_root[n][k-pair] = x[n] @ W_root1 + b1 (f32x2 pairs)
        int idx = (warp - 1) * 32 + lane;                 // 0..63
        for (int o = idx; o < NPG * 8; o += 64) {         // 432 float2 outputs
            int n = o >> 3, j = o & 7;                    // node, k-pair
            float4 X0 = sx4[n * 2], X1 = sx4[n * 2 + 1];
            float xf[8] = {X0.x, X0.y, X0.z, X0.w, X1.x, X1.y, X1.z, X1.w};
            unsigned long long acc = *(const unsigned long long*)(b1s + 2 * j);
            #pragma unroll
            for (int f = 0; f < 8; f++) {
                unsigned long long wd = *(const unsigned long long*)(w_root1 + f * 16 + 2 * j);
                fma2(acc, pk2(xf[f], xf[f]), wd);
            }
            *(float2*)(s_yroot + n * 16 + 2 * j) = upk(acc);
        }
    }
    __syncthreads();

    // ---------------- Phase 2: fused conv1 agg + h1 + z (register pair chain) ----------------
    if (t < NPG * 2) {
        const int n = t >> 1, half = t & 1;
        const unsigned mk = (t < 96) ? 0xffffffffu : 0x00000fffu;  // active lanes in my warp

        // (a) gather my 4 agg dims over this node's in-edges
        float4 agg = make_float4(0.f, 0.f, 0.f, 0.f);
        const int i0 = s_start[n], i1 = s_start[n + 1];
        for (int i = i0; i < i1; i++) {
            float2 e2 = s_sedge[i];
            int s = __float_as_int(e2.y);
            float w = e2.x;
            float4 xv = sx4[s * 2 + half];
            agg.x += w * xv.x; agg.y += w * xv.y; agg.z += w * xv.z; agg.w += w * xv.w;
        }

        // (b) pair-exchange -> full agg[8]
        float4 aggO;
        aggO.x = __shfl_xor_sync(mk, agg.x, 1);
        aggO.y = __shfl_xor_sync(mk, agg.y, 1);
        aggO.z = __shfl_xor_sync(mk, agg.z, 1);
        aggO.w = __shfl_xor_sync(mk, agg.w, 1);
        float a8[8];
        if (half == 0) {
            a8[0] = agg.x;  a8[1] = agg.y;  a8[2] = agg.z;  a8[3] = agg.w;
            a8[4] = aggO.x; a8[5] = aggO.y; a8[6] = aggO.z; a8[7] = aggO.w;
        } else {
            a8[0] = aggO.x; a8[1] = aggO.y; a8[2] = aggO.z; a8[3] = aggO.w;
            a8[4] = agg.x;  a8[5] = agg.y;  a8[6] = agg.z;  a8[7] = agg.w;
        }

        // (c) my 8 h1 outputs: k in [half*8, half*8+8); acc init = y_root (has b1)
        unsigned long long acc[4];
        #pragma unroll
        for (int j = 0; j < 4; j++)
            acc[j] = *(const unsigned long long*)(s_yroot + n * 16 + half * 8 + 2 * j);
        #pragma unroll
        for (int f = 0; f < 8; f++) {
            unsigned long long ad = pk2(a8[f], a8[f]);
            const ulonglong2* wr = (const ulonglong2*)(w_rel1 + f * 16 + half * 8);
            ulonglong2 w0 = wr[0], w1 = wr[1];
            fma2(acc[0], ad, w0.x); fma2(acc[1], ad, w0.y);
            fma2(acc[2], ad, w1.x); fma2(acc[3], ad, w1.y);
        }
        float h[8];
        #pragma unroll
        for (int j = 0; j < 4; j++) {
            float2 v = upk(acc[j]);
            h[2 * j]     = fmaxf(v.x, 0.f);
            h[2 * j + 1] = fmaxf(v.y, 0.f);
        }

        // (d) z partials over my k-half: z_rel = h1@W_rel2, z_root = h1@W_root2 (+b2 on half0)
        unsigned long long zr0 = 0ULL, zr1 = 0ULL, zo0, zo1;
        if (half == 0) {
            ulonglong2 bb = *(const ulonglong2*)b2s;
            zo0 = bb.x; zo1 = bb.y;
        } else { zo0 = 0ULL; zo1 = 0ULL; }
        #pragma unroll
        for (int kk = 0; kk < 8; kk++) {
            int k = half * 8 + kk;
            unsigned long long hd = pk2(h[kk], h[kk]);
            ulonglong2 wr = *(const ulonglong2*)(w_rel2 + k * 4);
            fma2(zr0, hd, wr.x); fma2(zr1, hd, wr.y);
            ulonglong2 wo = *(const ulonglong2*)(w_root2 + k * 4);
            fma2(zo0, hd, wo.x); fma2(zo1, hd, wo.y);
        }
        // (e) pair-combine and write z
        float2 a0 = upk(zr0), a1 = upk(zr1), b0 = upk(zo0), b1v = upk(zo1);
        float zb[8] = {a0.x, a0.y, a1.x, a1.y, b0.x, b0.y, b1v.x, b1v.y};
        #pragma unroll
        for (int j = 0; j < 8; j++)
            zb[j] += __shfl_xor_sync(mk, zb[j], 1);
        if (half == 0) s_zrel[n]  = make_float4(zb[0], zb[1], zb[2], zb[3]);
        else           s_zroot[n] = make_float4(zb[4], zb[5], zb[6], zb[7]);
    }
    __syncthreads();

    // ---------------- Phase 3: conv2 aggregation (2-wide) + write g_act ----------------
    if (t < NPG * 2) {
        int n = t >> 1, half = t & 1;
        const float* zr = (const float*)s_zrel;
        float2 acc = *(const float2*)((const float*)(s_zroot + n) + half * 2);
        int i0 = s_start[n], i1 = s_start[n + 1];
        for (int i = i0; i < i1; i++) {
            float2 e2 = s_sedge[i];
            int s = __float_as_int(e2.y);
            float w = e2.x;
            float2 z = *(const float2*)(zr + s * 4 + half * 2);
            acc.x += w * z.x;
            acc.y += w * z.y;
        }
        *(float2*)(g_act + (size_t)g * ACTW + n * 4 + half * 2) =
            make_float2(fmaxf(acc.x, 0.f), fmaxf(acc.y, 0.f));
    }
}

// =================================================================
// K2: out = sigmoid(relu(act @ Wo1 + bo1) @ Wo2 + bo2)
// 64-row x 128-col tile per block (grid 512 x 128 thr), 8x8 thread tile,
// double-buffered smem. f32x2 packed FMAs; fused epilogue. (R5/R8, ~59us)
// =================================================================
__global__ __launch_bounds__(128)
void k2_outmlp(const float* __restrict__ Wo1,   // [226][128]
               const float* __restrict__ bo1,   // [128]
               const float* __restrict__ Wo2,   // [128]
               const float* __restrict__ bo2,   // [1]
               float* __restrict__ out)         // [B]
{
    __shared__ __align__(16) float sA[2][KCH * 64];
    __shared__ __align__(16) float sW[2][KCH * 128];
    const int tid = threadIdx.x;
    const int tx = tid & 15, ty = tid >> 4;
    const int blockRow = blockIdx.x * 64;
    const int r0 = ty * 8, c0 = tx * 8;

    unsigned long long acc[8][4];
    #pragma unroll
    for (int r = 0; r < 8; r++)
        #pragma unroll
        for (int cp = 0; cp < 4; cp++) acc[r][cp] = 0ULL;

    auto load_chunk = [&](int kb, int buf) {
        const int k0 = kb * KCH;
        #pragma unroll
        for (int q = 0; q < 2; q++) {                      // A: 64 rows x 16 k
            int idx = tid + q * 128;
            int row = idx & 63, kq = idx >> 6;
            float4 v = *(const float4*)(g_act + (size_t)(blockRow + row) * ACTW + k0 + kq * 4);
            sA[buf][(kq * 4 + 0) * 64 + row] = v.x;
            sA[buf][(kq * 4 + 1) * 64 + row] = v.y;
            sA[buf][(kq * 4 + 2) * 64 + row] = v.z;
            sA[buf][(kq * 4 + 3) * 64 + row] = v.w;
        }
        #pragma unroll
        for (int q = 0; q < 4; q++) {                      // W: 16 k x 128 cols
            int idx = tid + q * 128;
            int kk = idx >> 5, c4 = (idx & 31) * 4;
            int k = k0 + kk;
            float4 w = (k < 226) ? *(const float4*)(Wo1 + (size_t)k * 128 + c4)
                                 : make_float4(0.f, 0.f, 0.f, 0.f);
            *(float4*)(sW[buf] + kk * 128 + c4) = w;
        }
    };

    load_chunk(0, 0);
    __syncthreads();

    for (int kb = 0; kb < 15; kb++) {
        const int cur = kb & 1;
        if (kb < 14) load_chunk(kb + 1, cur ^ 1);
        #pragma unroll
        for (int kk = 0; kk < KCH; kk++) {
            float4 aLo = *(const float4*)(sA[cur] + kk * 64 + r0);
            float4 aHi = *(const float4*)(sA[cur] + kk * 64 + r0 + 4);
            ulonglong2 wA = *(const ulonglong2*)(sW[cur] + kk * 128 + c0);
            ulonglong2 wB = *(const ulonglong2*)(sW[cur] + kk * 128 + c0 + 4);
            float ar[8] = {aLo.x, aLo.y, aLo.z, aLo.w, aHi.x, aHi.y, aHi.z, aHi.w};
            #pragma unroll
            for (int r = 0; r < 8; r++) {
                unsigned long long ad = pk2(ar[r], ar[r]);
                fma2(acc[r][0], ad, wA.x);
                fma2(acc[r][1], ad, wA.y);
                fma2(acc[r][2], ad, wB.x);
                fma2(acc[r][3], ad, wB.y);
            }
        }
        __syncthreads();
    }

    // Epilogue: relu + dot with Wo2, reduce across 16 col-threads, sigmoid.
    float b1v[8], w2v[8];
    #pragma unroll
    for (int c = 0; c < 8; c++) { b1v[c] = bo1[c0 + c]; w2v[c] = Wo2[c0 + c]; }
    float p[8];
    #pragma unroll
    for (int r = 0; r < 8; r++) {
        p[r] = 0.f;
        #pragma unroll
        for (int cp = 0; cp < 4; cp++) {
            float2 v = upk(acc[r][cp]);
            p[r] += fmaxf(v.x + b1v[2 * cp],     0.f) * w2v[2 * cp];
            p[r] += fmaxf(v.y + b1v[2 * cp + 1], 0.f) * w2v[2 * cp + 1];
        }
    }
    #pragma unroll
    for (int r = 0; r < 8; r++) {
        #pragma unroll
        for (int off = 8; off > 0; off >>= 1)
            p[r] += __shfl_xor_sync(0xffffffffu, p[r], off, 16);
    }
    if (tx == 0) {
        float bb = bo2[0];
        #pragma unroll
        for (int r = 0; r < 8; r++) {
            float z = p[r] + bb;
            out[blockRow + r0 + r] = 1.f / (1.f + expf(-z));
        }
    }
}

extern "C" void kernel_launch(void* const* d_in, const int* in_sizes, int n_in,
                              void* d_out, int out_size)
{
    const float* x       = (const float*)d_in[0];
    const int*   ei      = (const int*)  d_in[1];
    const float* ea      = (const float*)d_in[2];
    const float* gf      = (const float*)d_in[3];
    const float* W_rel1  = (const float*)d_in[4];
    const float* b1      = (const float*)d_in[5];
    const float* W_root1 = (const float*)d_in[6];
    const float* W_rel2  = (const float*)d_in[7];
    const float* b2      = (const float*)d_in[8];
    const float* W_root2 = (const float*)d_in[9];
    const float* Wg1     = (const float*)d_in[10];
    const float* bg1     = (const float*)d_in[11];
    const float* Wg2     = (const float*)d_in[12];
    const float* bg2     = (const float*)d_in[13];
    const float* Wg3     = (const float*)d_in[14];
    const float* bg3     = (const float*)d_in[15];
    const float* Wo1     = (const float*)d_in[16];
    const float* bo1     = (const float*)d_in[17];
    const float* Wo2     = (const float*)d_in[18];
    const float* bo2     = (const float*)d_in[19];
    float* out = (float*)d_out;

    k1_graph<<<BGR, 128>>>(x, ei, ea, gf,
                           W_rel1, b1, W_root1,
                           W_rel2, b2, W_root2,
                           Wg1, bg1, Wg2, bg2, Wg3, bg3);
    k2_outmlp<<<BGR / 64, 128>>>(Wo1, bo1, Wo2, bo2, out);
}